// round 13
// baseline (speedup 1.0000x reference)
#include <cuda_runtime.h>
#include <cuda_bf16.h>
#include <cstdint>

#define HW 25600
#define P4 102400   // 4 images * HW  (img 0,1 = x_l b0,b1 ; img 2,3 = x_r b0,b1)
#define P2 51200    // 2 batches * HW

// ------------------------- scratch (__device__ globals) -------------------------
__device__ __nv_bfloat16 g_h[(size_t)P4 * 128];   // LN1+pw1 out, NHWC (bf16)
__device__ __nv_bfloat16 g_v[(size_t)P4 * 128];   // value proj (bf16)
__device__ __nv_bfloat16 g_om[(size_t)P4 * 112];  // offset/mask proj (bf16)
__device__ __nv_bfloat16 g_f[(size_t)P4 * 64];    // gated branch features (bf16)
__device__ float g_y[(size_t)P2 * 128];           // [y_l(64) ; y_r(64)] NHWC per batch
__device__ float g_part[256];                     // pooling sums [img][64]
__device__ float g_s[256];                        // SCA scale s[b][128]
__device__ __nv_bfloat16 g_wp[75776];             // packed bf16 weights

// packed-weight segment offsets (elements)
#define OFF_PW1   0
#define OFF_VAL   8192
#define OFF_OM    24576
#define OFF_OUTP  38912
#define OFF_C4    55296
#define OFF_C5    71680

// ------------------------- bf16 helpers -------------------------
__device__ __forceinline__ uint32_t pk(float a, float b) {
    __nv_bfloat162 t = __floats2bfloat162_rn(a, b);
    return *reinterpret_cast<uint32_t*>(&t);
}
__device__ __forceinline__ float2 upk(uint32_t u) {
    __nv_bfloat162 t = *reinterpret_cast<__nv_bfloat162*>(&u);
    return __bfloat1622float2(t);
}
__device__ __forceinline__ float4 ld4bf(const __nv_bfloat16* p) {
    uint2 u = *(const uint2*)p;
    float2 fa = upk(u.x), fb = upk(u.y);
    return make_float4(fa.x, fa.y, fb.x, fb.y);
}
__device__ __forceinline__ void mma_bf16(float* c, const uint32_t* a, const uint32_t* b) {
    asm volatile(
        "mma.sync.aligned.m16n8k16.row.col.f32.bf16.bf16.f32 "
        "{%0,%1,%2,%3}, {%4,%5,%6,%7}, {%8,%9}, {%0,%1,%2,%3};"
        : "+f"(c[0]), "+f"(c[1]), "+f"(c[2]), "+f"(c[3])
        : "r"(a[0]), "r"(a[1]), "r"(a[2]), "r"(a[3]), "r"(b[0]), "r"(b[1]));
}

// ------------------------- weight pack + g_part zero -------------------------
__global__ void __launch_bounds__(256) k_pack(const float* __restrict__ pw1,
                                              const float* __restrict__ val,
                                              const float* __restrict__ om,
                                              const float* __restrict__ outp,
                                              const float* __restrict__ c4,
                                              const float* __restrict__ c5) {
    int i = blockIdx.x * 256 + threadIdx.x;
    if (blockIdx.x == 0) g_part[threadIdx.x] = 0.f;
    if (i >= 75776) return;
    float v;
    if (i < OFF_VAL)       v = pw1[i - OFF_PW1];
    else if (i < OFF_OM)   v = val[i - OFF_VAL];
    else if (i < OFF_OUTP) v = om[i - OFF_OM];
    else if (i < OFF_C4)   v = outp[i - OFF_OUTP];
    else if (i < OFF_C5)   v = c4[i - OFF_C4];
    else                   v = c5[i - OFF_C5];
    g_wp[i] = __float2bfloat16_rn(v);
}

// ------------------------- kernel 1: LN + pw1 + val GEMM fused -------------------------
__global__ void __launch_bounds__(256) k_lnpw1v(const float* __restrict__ x_l,
                                                const float* __restrict__ x_r,
                                                const float* __restrict__ g1,
                                                const float* __restrict__ B1,
                                                const float* __restrict__ Bv) {
    extern __shared__ float sm[];
    float* Xf = sm;                            // 64*68 fp32
    float* mr = Xf + 64 * 68;                  // 128
    uint32_t* Xb = (uint32_t*)(mr + 128);      // 64*36 (bf16 pairs, K=64)
    uint32_t* Wb = Xb + 64 * 36;               // 128*36 (pw1 weights)
    uint32_t* Wv = Wb + 128 * 36;              // 128*68 (val weights, K=128)
    uint32_t* Hb = Wv + 128 * 68;              // 64*68  (h tile bf16)
    int tid = threadIdx.x;
    int base = blockIdx.x * 64;
    int img = base / HW;
    int pos = base - img * HW;
    const float* xp = (img < 2) ? (x_l + (size_t)img * HW * 64)
                                : (x_r + (size_t)(img - 2) * HW * 64);
    for (int i = tid; i < 64 * 64; i += 256) {
        int c = i >> 6, p = i & 63;
        Xf[p * 68 + c] = xp[(size_t)c * HW + pos + p];
    }
    const uint4* Wp1 = (const uint4*)(g_wp + OFF_PW1);
    for (int i = tid; i < 1024; i += 256) {
        int row = i >> 3, q = i & 7;
        uint4 u = __ldg(&Wp1[row * 8 + q]);
        Wb[row * 36 + q * 4]     = u.x;
        Wb[row * 36 + q * 4 + 1] = u.y;
        Wb[row * 36 + q * 4 + 2] = u.z;
        Wb[row * 36 + q * 4 + 3] = u.w;
    }
    const uint4* Wpv = (const uint4*)(g_wp + OFF_VAL);
    for (int i = tid; i < 2048; i += 256) {
        int row = i >> 4, q = i & 15;
        uint4 u = __ldg(&Wpv[row * 16 + q]);
        Wv[row * 68 + q * 4]     = u.x;
        Wv[row * 68 + q * 4 + 1] = u.y;
        Wv[row * 68 + q * 4 + 2] = u.z;
        Wv[row * 68 + q * 4 + 3] = u.w;
    }
    __syncthreads();
    if (tid < 64) {
        float s = 0.f, sq = 0.f;
        for (int c = 0; c < 64; c++) { float v = Xf[tid * 68 + c]; s += v; sq += v * v; }
        float m = s * (1.f / 64.f);
        float var = sq * (1.f / 64.f) - m * m;
        mr[tid] = m; mr[64 + tid] = rsqrtf(var + 1e-5f);
    }
    __syncthreads();
    for (int i = tid; i < 64 * 32; i += 256) {
        int p = i >> 5, q = i & 31;
        int k0 = q * 2;
        float f0 = (Xf[p * 68 + k0] - mr[p]) * mr[64 + p] * __ldg(&g1[k0]);
        float f1 = (Xf[p * 68 + k0 + 1] - mr[p]) * mr[64 + p] * __ldg(&g1[k0 + 1]);
        Xb[p * 36 + q] = pk(f0, f1);
    }
    __syncthreads();
    int wid = tid >> 5, lane = tid & 31;
    int wm = wid & 1, wn = wid >> 1;
    int gid = lane >> 2, tig = lane & 3;
    // ---- phase 1: h ----
    {
        float c[2][4][4];
#pragma unroll
        for (int nt = 0; nt < 4; nt++) {
            int o = wn * 32 + nt * 8 + 2 * tig;
            float b0 = B1[o], b1 = B1[o + 1];
#pragma unroll
            for (int mt = 0; mt < 2; mt++) {
                c[mt][nt][0] = b0; c[mt][nt][1] = b1;
                c[mt][nt][2] = b0; c[mt][nt][3] = b1;
            }
        }
#pragma unroll
        for (int kw = 0; kw < 32; kw += 8) {
            uint32_t A[2][4];
#pragma unroll
            for (int mt = 0; mt < 2; mt++) {
                int r = wm * 32 + mt * 16 + gid;
                A[mt][0] = Xb[r * 36 + kw + tig];
                A[mt][1] = Xb[(r + 8) * 36 + kw + tig];
                A[mt][2] = Xb[r * 36 + kw + 4 + tig];
                A[mt][3] = Xb[(r + 8) * 36 + kw + 4 + tig];
            }
#pragma unroll
            for (int nt = 0; nt < 4; nt++) {
                int n = wn * 32 + nt * 8 + gid;
                uint32_t Bf[2];
                Bf[0] = Wb[n * 36 + kw + tig];
                Bf[1] = Wb[n * 36 + kw + 4 + tig];
#pragma unroll
                for (int mt = 0; mt < 2; mt++) mma_bf16(c[mt][nt], A[mt], Bf);
            }
        }
        uint32_t* gh = (uint32_t*)g_h;
#pragma unroll
        for (int mt = 0; mt < 2; mt++) {
            int rl = wm * 32 + mt * 16 + gid;
            size_t r0 = base + rl;
#pragma unroll
            for (int nt = 0; nt < 4; nt++) {
                int o = wn * 32 + nt * 8 + 2 * tig;
                uint32_t w0 = pk(c[mt][nt][0], c[mt][nt][1]);
                uint32_t w1 = pk(c[mt][nt][2], c[mt][nt][3]);
                gh[r0 * 64 + o / 2] = w0;
                gh[(r0 + 8) * 64 + o / 2] = w1;
                Hb[rl * 68 + o / 2] = w0;
                Hb[(rl + 8) * 68 + o / 2] = w1;
            }
        }
    }
    __syncthreads();
    // ---- phase 2: v ----
    {
        float c[2][4][4];
#pragma unroll
        for (int nt = 0; nt < 4; nt++) {
            int o = wn * 32 + nt * 8 + 2 * tig;
            float b0 = Bv[o], b1 = Bv[o + 1];
#pragma unroll
            for (int mt = 0; mt < 2; mt++) {
                c[mt][nt][0] = b0; c[mt][nt][1] = b1;
                c[mt][nt][2] = b0; c[mt][nt][3] = b1;
            }
        }
#pragma unroll
        for (int kw = 0; kw < 64; kw += 8) {
            uint32_t A[2][4];
#pragma unroll
            for (int mt = 0; mt < 2; mt++) {
                int r = wm * 32 + mt * 16 + gid;
                A[mt][0] = Hb[r * 68 + kw + tig];
                A[mt][1] = Hb[(r + 8) * 68 + kw + tig];
                A[mt][2] = Hb[r * 68 + kw + 4 + tig];
                A[mt][3] = Hb[(r + 8) * 68 + kw + 4 + tig];
            }
#pragma unroll
            for (int nt = 0; nt < 4; nt++) {
                int n = wn * 32 + nt * 8 + gid;
                uint32_t Bf[2];
                Bf[0] = Wv[n * 68 + kw + tig];
                Bf[1] = Wv[n * 68 + kw + 4 + tig];
#pragma unroll
                for (int mt = 0; mt < 2; mt++) mma_bf16(c[mt][nt], A[mt], Bf);
            }
        }
        uint32_t* gv = (uint32_t*)g_v;
#pragma unroll
        for (int mt = 0; mt < 2; mt++) {
            size_t r0 = base + wm * 32 + mt * 16 + gid;
#pragma unroll
            for (int nt = 0; nt < 4; nt++) {
                int o = wn * 32 + nt * 8 + 2 * tig;
                gv[r0 * 64 + o / 2] = pk(c[mt][nt][0], c[mt][nt][1]);
                gv[(r0 + 8) * 64 + o / 2] = pk(c[mt][nt][2], c[mt][nt][3]);
            }
        }
    }
}

// ------------------------- fused: depthwise 3x3 + om GEMM (128px x 112, K=128) -------------------------
__global__ void __launch_bounds__(256) k_dwom(const float* __restrict__ Wd,
                                              const float* __restrict__ Bd,
                                              const float* __restrict__ Bb) {
    const int N = 112;
    extern __shared__ uint32_t smu[];
    uint32_t* Xu = smu;                        // 128*68 words (dwc out, bf16)
    uint32_t* Wu = smu + 128 * 68;             // 128*68 words (om weights)
    float* wts = (float*)(Wu + 128 * 68);      // 9*128 dwc weights
    float* bds = wts + 9 * 128;                // 128 dwc bias
    int tid = threadIdx.x;
    size_t base = (size_t)blockIdx.x * 128;
    int img = (int)(base / HW);
    int pbase = (int)(base - (size_t)img * HW);
    // dwc weights + bias
    for (int i = tid; i < 9 * 128; i += 256) wts[i] = __ldg(&Wd[i]);
    if (tid < 128) bds[tid] = __ldg(&Bd[tid]);
    // om weights
    const uint4* Wg = (const uint4*)(g_wp + OFF_OM);
    for (int i = tid; i < 2048; i += 256) {
        int row = i >> 4, q = i & 15;
        uint4 u = make_uint4(0u, 0u, 0u, 0u);
        if (row < N) u = __ldg(&Wg[row * 16 + q]);
        Wu[row * 68 + q * 4]     = u.x;
        Wu[row * 68 + q * 4 + 1] = u.y;
        Wu[row * 68 + q * 4 + 2] = u.z;
        Wu[row * 68 + q * 4 + 3] = u.w;
    }
    __syncthreads();
    // depthwise 3x3 into Xu (warp = one px per pass; lane = 4-channel group -> coalesced row reads)
    const __nv_bfloat16* hb = g_h + (size_t)img * HW * 128;
    for (int it = tid; it < 4096; it += 256) {
        int px = it >> 5;       // 0..127
        int wg = it & 31;       // channel group (4 ch)
        int c0 = wg * 4;
        int pos = pbase + px;
        int hh = pos / 160, ww = pos - hh * 160;
        float a0 = bds[c0], a1 = bds[c0 + 1], a2 = bds[c0 + 2], a3 = bds[c0 + 3];
#pragma unroll
        for (int dy = 0; dy < 3; dy++) {
            int y = hh + dy - 1;
            if ((unsigned)y >= 160u) continue;
            const __nv_bfloat16* rowp = hb + ((size_t)y * 160) * 128 + c0;
#pragma unroll
            for (int dx = 0; dx < 3; dx++) {
                int x = ww + dx - 1;
                if ((unsigned)x >= 160u) continue;
                float4 v = ld4bf(&rowp[(size_t)x * 128]);
                float4 wv = *(const float4*)&wts[(dy * 3 + dx) * 128 + c0];
                a0 += v.x * wv.x; a1 += v.y * wv.y; a2 += v.z * wv.z; a3 += v.w * wv.w;
            }
        }
        Xu[px * 68 + wg * 2]     = pk(a0, a1);
        Xu[px * 68 + wg * 2 + 1] = pk(a2, a3);
    }
    __syncthreads();
    int wid = tid >> 5, lane = tid & 31;
    int wm = wid & 3, wn = wid >> 2;
    int gid = lane >> 2, tig = lane & 3;
    float c[2][8][4];
#pragma unroll
    for (int nt = 0; nt < 8; nt++) {
        int o = wn * 64 + nt * 8 + 2 * tig;
        float b0 = (o < N) ? Bb[o] : 0.f;
        float b1 = (o + 1 < N) ? Bb[o + 1] : 0.f;
#pragma unroll
        for (int mt = 0; mt < 2; mt++) {
            c[mt][nt][0] = b0; c[mt][nt][1] = b1;
            c[mt][nt][2] = b0; c[mt][nt][3] = b1;
        }
    }
#pragma unroll
    for (int kw = 0; kw < 64; kw += 8) {
        uint32_t A[2][4];
#pragma unroll
        for (int mt = 0; mt < 2; mt++) {
            int r = wm * 32 + mt * 16 + gid;
            A[mt][0] = Xu[r * 68 + kw + tig];
            A[mt][1] = Xu[(r + 8) * 68 + kw + tig];
            A[mt][2] = Xu[r * 68 + kw + 4 + tig];
            A[mt][3] = Xu[(r + 8) * 68 + kw + 4 + tig];
        }
        uint32_t Bf[8][2];
#pragma unroll
        for (int nt = 0; nt < 8; nt++) {
            int n = wn * 64 + nt * 8 + gid;
            Bf[nt][0] = Wu[n * 68 + kw + tig];
            Bf[nt][1] = Wu[n * 68 + kw + 4 + tig];
        }
#pragma unroll
        for (int mt = 0; mt < 2; mt++)
#pragma unroll
            for (int nt = 0; nt < 8; nt++)
                mma_bf16(c[mt][nt], A[mt], Bf[nt]);
    }
    uint32_t* Yu = (uint32_t*)g_om;
#pragma unroll
    for (int mt = 0; mt < 2; mt++) {
        size_t r0 = base + wm * 32 + mt * 16 + gid;
#pragma unroll
        for (int nt = 0; nt < 8; nt++) {
            int o = wn * 64 + nt * 8 + 2 * tig;
            if (o < N) {
                Yu[r0 * 56 + o / 2] = pk(c[mt][nt][0], c[mt][nt][1]);
                Yu[(r0 + 8) * 56 + o / 2] = pk(c[mt][nt][2], c[mt][nt][3]);
            }
        }
    }
}

// ------------------------- fused: deform sample + outp GEMM + gate + pool partial -------------------------
__device__ __forceinline__ void fma4(float4& a, float w, const float4 v) {
    a.x += w * v.x; a.y += w * v.y; a.z += w * v.z; a.w += w * v.w;
}

__global__ void __launch_bounds__(256) k_souter(const float* __restrict__ Bo) {
    extern __shared__ uint32_t smu[];
    uint32_t* Wb = smu;                         // 128*68 words
    uint32_t* Xb = smu + 128 * 68;              // 64*68 words
    uint32_t* OMt = Xb + 64 * 68;               // 64*56 words (om tile bf16)
    float* pacc = (float*)(OMt + 64 * 56);      // 64 floats
    int tid = threadIdx.x;
    int base = blockIdx.x * 64;
    int img = base / HW;
    int pbase = base - img * HW;
    if (tid < 64) pacc[tid] = 0.f;
    const uint4* Wg = (const uint4*)(g_wp + OFF_OUTP);
    for (int i = tid; i < 2048; i += 256) {
        int row = i >> 4, q = i & 15;
        uint4 u = __ldg(&Wg[row * 16 + q]);
        Wb[row * 68 + q * 4]     = u.x;
        Wb[row * 68 + q * 4 + 1] = u.y;
        Wb[row * 68 + q * 4 + 2] = u.z;
        Wb[row * 68 + q * 4 + 3] = u.w;
    }
    {
        const uint32_t* oms = (const uint32_t*)g_om + ((size_t)img * HW + pbase) * 56;
        for (int i = tid; i < 3584; i += 256) OMt[i] = __ldg(&oms[i]);
    }
    __syncthreads();
    int wrp = tid >> 5, lane = tid & 31;
    int g = lane >> 3, c4 = lane & 7;
    const __nv_bfloat16* vg = g_v + (size_t)img * HW * 128 + g * 32 + c4 * 4;
    for (int p8 = 0; p8 < 8; p8++) {
        int px = wrp * 8 + p8;
        int pos = pbase + px;
        int hh = pos / 160, ww = pos - hh * 160;
        const uint32_t* omp = OMt + px * 56;
        float4 acc = make_float4(0.f, 0.f, 0.f, 0.f);
#pragma unroll
        for (int k = 0; k < 9; k++) {
            int j0 = g * 27 + 3 * k;
            int w0 = j0 >> 1;
            float2 f0 = upk(omp[w0]);
            float2 f1 = upk(omp[w0 + 1]);
            bool odd = ((g + k) & 1);
            float ox = odd ? f0.y : f0.x;
            float oy = odd ? f1.x : f0.y;
            float mk = odd ? f1.y : f1.x;
            float fx = (float)(ww + (k % 3) - 1) + ox;
            float fy = (float)(hh + (k / 3) - 1) + oy;
            float x0f = floorf(fx), y0f = floorf(fy);
            float tx = fx - x0f, ty = fy - y0f;
            int ix = (int)x0f, iy = (int)y0f;
            float w00 = (1.f - tx) * (1.f - ty) * mk;
            float w01 = tx * (1.f - ty) * mk;
            float w10 = (1.f - tx) * ty * mk;
            float w11 = tx * ty * mk;
            if ((unsigned)iy < 160u) {
                if ((unsigned)ix < 160u)
                    fma4(acc, w00, ld4bf(&vg[(size_t)(iy * 160 + ix) * 128]));
                if ((unsigned)(ix + 1) < 160u)
                    fma4(acc, w01, ld4bf(&vg[(size_t)(iy * 160 + ix + 1) * 128]));
            }
            if ((unsigned)(iy + 1) < 160u) {
                if ((unsigned)ix < 160u)
                    fma4(acc, w10, ld4bf(&vg[(size_t)((iy + 1) * 160 + ix) * 128]));
                if ((unsigned)(ix + 1) < 160u)
                    fma4(acc, w11, ld4bf(&vg[(size_t)((iy + 1) * 160 + ix + 1) * 128]));
            }
        }
        Xb[px * 68 + lane * 2] = pk(acc.x, acc.y);
        Xb[px * 68 + lane * 2 + 1] = pk(acc.z, acc.w);
    }
    __syncthreads();
    int wm = wrp & 1, wn = wrp >> 1;
    int gid = lane >> 2, tig = lane & 3;
    float c[2][4][4];
#pragma unroll
    for (int nt = 0; nt < 4; nt++) {
        int o = wn * 16 + (nt & 1) * 8 + (nt >> 1) * 64 + 2 * tig;
        float b0 = Bo[o], b1 = Bo[o + 1];
#pragma unroll
        for (int mt = 0; mt < 2; mt++) {
            c[mt][nt][0] = b0; c[mt][nt][1] = b1;
            c[mt][nt][2] = b0; c[mt][nt][3] = b1;
        }
    }
#pragma unroll
    for (int kw = 0; kw < 64; kw += 8) {
        uint32_t A[2][4];
#pragma unroll
        for (int mt = 0; mt < 2; mt++) {
            int r = wm * 32 + mt * 16 + gid;
            A[mt][0] = Xb[r * 68 + kw + tig];
            A[mt][1] = Xb[(r + 8) * 68 + kw + tig];
            A[mt][2] = Xb[r * 68 + kw + 4 + tig];
            A[mt][3] = Xb[(r + 8) * 68 + kw + 4 + tig];
        }
#pragma unroll
        for (int nt = 0; nt < 4; nt++) {
            int n = wn * 16 + (nt & 1) * 8 + (nt >> 1) * 64 + gid;
            uint32_t Bf[2];
            Bf[0] = Wb[n * 68 + kw + tig];
            Bf[1] = Wb[n * 68 + kw + 4 + tig];
#pragma unroll
            for (int mt = 0; mt < 2; mt++) mma_bf16(c[mt][nt], A[mt], Bf);
        }
    }
    uint32_t* gf = (uint32_t*)g_f;
#pragma unroll
    for (int ntp = 0; ntp < 2; ntp++) {
        int o = wn * 16 + ntp * 8 + 2 * tig;
        float s0 = 0.f, s1 = 0.f;
#pragma unroll
        for (int mt = 0; mt < 2; mt++) {
            size_t r0 = base + wm * 32 + mt * 16 + gid;
            float p00 = c[mt][ntp][0] * c[mt][ntp + 2][0];
            float p01 = c[mt][ntp][1] * c[mt][ntp + 2][1];
            float p10 = c[mt][ntp][2] * c[mt][ntp + 2][2];
            float p11 = c[mt][ntp][3] * c[mt][ntp + 2][3];
            gf[r0 * 32 + o / 2] = pk(p00, p01);
            gf[(r0 + 8) * 32 + o / 2] = pk(p10, p11);
            s0 += p00 + p10;
            s1 += p01 + p11;
        }
        atomicAdd(&pacc[o], s0);
        atomicAdd(&pacc[o + 1], s1);
    }
    __syncthreads();
    if (tid < 64) atomicAdd(&g_part[img * 64 + tid], pacc[tid]);
}

// ------------------------- finish pooling + SCA projection -------------------------
__global__ void __launch_bounds__(256) k_sca(const float* __restrict__ sw, const float* __restrict__ sb) {
    __shared__ float shp[256];
    int tid = threadIdx.x;
    int b = tid >> 7, c = tid & 127;
    int img = (c < 64) ? b : (2 + b);
    int cc = c & 63;
    shp[tid] = g_part[img * 64 + cc] * (1.f / (float)HW);
    __syncthreads();
    float acc = __ldg(&sb[c]);
    for (int k = 0; k < 128; k++) acc += shp[b * 128 + k] * __ldg(&sw[c * 128 + k]);
    g_s[tid] = acc;
}

// ------------------------- SCA-folded conv3 + dual residual -> g_y -------------------------
__global__ void __launch_bounds__(256) k_conv3_y(const float* __restrict__ W3,
                                                 const float* __restrict__ B3,
                                                 const float* __restrict__ beta,
                                                 const float* __restrict__ x_l,
                                                 const float* __restrict__ x_r) {
    extern __shared__ float sm[];
    float* Fs = sm;              // 64*132
    float* W3s = sm + 64 * 132;  // 64*128 (scale-folded)
    int tid = threadIdx.x;
    int base = blockIdx.x * 64;
    int b = base / HW;
    int pos = base - b * HW;
    const uint32_t* gf = (const uint32_t*)g_f;
    for (int i = tid; i < 64 * 64; i += 256) {
        int p = i >> 6, w = i & 63;
        int imgX = (w < 32) ? b : (2 + b);
        float2 f = upk(gf[((size_t)imgX * HW + pos + p) * 32 + (w & 31)]);
        Fs[p * 132 + 2 * w] = f.x;
        Fs[p * 132 + 2 * w + 1] = f.y;
    }
    for (int i = tid; i < 64 * 128; i += 256) {
        int o = i & 127;
        W3s[i] = W3[i] * g_s[b * 128 + o];
    }
    __syncthreads();
    int pr = tid & 15, og = tid >> 4;
    float acc[4][4];
#pragma unroll
    for (int j = 0; j < 4; j++) {
        float bv = B3[og * 4 + j];
#pragma unroll
        for (int i = 0; i < 4; i++) acc[i][j] = bv;
    }
#pragma unroll 4
    for (int k = 0; k < 128; k += 4) {
        float4 xv[4];
#pragma unroll
        for (int i = 0; i < 4; i++) xv[i] = *(const float4*)&Fs[(pr + 16 * i) * 132 + k];
#pragma unroll
        for (int j = 0; j < 4; j++) {
            float4 wv = *(const float4*)&W3s[(og * 4 + j) * 128 + k];
#pragma unroll
            for (int i = 0; i < 4; i++)
                acc[i][j] += xv[i].x * wv.x + xv[i].y * wv.y + xv[i].z * wv.z + xv[i].w * wv.w;
        }
    }
#pragma unroll
    for (int i = 0; i < 4; i++) {
        int p = pr + 16 * i;
#pragma unroll
        for (int j = 0; j < 4; j++) {
            int jj = og * 4 + j;
            float bt = __ldg(&beta[jj]);
            float x3 = acc[i][j] * bt;
            float xl = x_l[((size_t)b * 64 + jj) * HW + pos + p];
            float xr = x_r[((size_t)b * 64 + jj) * HW + pos + p];
            g_y[(size_t)(base + p) * 128 + jj] = xl + x3;
            g_y[(size_t)(base + p) * 128 + 64 + jj] = xr + x3;
        }
    }
}

// ------------------------- LN2 + conv4 + gate + conv5 + final residuals -> out -------------------------
__global__ void __launch_bounds__(256) k_ln2c4c5(const float* __restrict__ g2,
                                                 const float* __restrict__ B4,
                                                 const float* __restrict__ B5,
                                                 const float* __restrict__ gamma,
                                                 float* __restrict__ out) {
    extern __shared__ float sm[];
    float* Yf = sm;                                 // 64*132 fp32
    uint32_t* Yb = (uint32_t*)(sm + 64 * 132);      // 64*68 words
    uint32_t* Wb = Yb + 64 * 68;                    // 128*68 words (conv4)
    uint32_t* Zb = Wb + 128 * 68;                   // 64*36 words (zg bf16)
    uint32_t* W5b = Zb + 64 * 36;                   // 64*36 words (conv5)
    float* mr = (float*)(W5b + 64 * 36);            // 128
    int tid = threadIdx.x;
    int base = blockIdx.x * 64;
    int b = base / HW;
    int pos = base - b * HW;
    for (int i = tid; i < 64 * 128; i += 256) {
        int p = i >> 7, c = i & 127;
        Yf[p * 132 + c] = g_y[(size_t)(base + p) * 128 + c];
    }
    const uint4* Wg = (const uint4*)(g_wp + OFF_C4);
    for (int i = tid; i < 2048; i += 256) {
        int row = i >> 4, q = i & 15;
        uint4 u = __ldg(&Wg[row * 16 + q]);
        Wb[row * 68 + q * 4]     = u.x;
        Wb[row * 68 + q * 4 + 1] = u.y;
        Wb[row * 68 + q * 4 + 2] = u.z;
        Wb[row * 68 + q * 4 + 3] = u.w;
    }
    const uint4* W5g = (const uint4*)(g_wp + OFF_C5);
    for (int i = tid; i < 512; i += 256) {
        int row = i >> 3, q = i & 7;
        uint4 u = __ldg(&W5g[row * 8 + q]);
        W5b[row * 36 + q * 4]     = u.x;
        W5b[row * 36 + q * 4 + 1] = u.y;
        W5b[row * 36 + q * 4 + 2] = u.z;
        W5b[row * 36 + q * 4 + 3] = u.w;
    }
    __syncthreads();
    if (tid < 64) {
        float s = 0.f, sq = 0.f;
        for (int c = 0; c < 128; c++) { float v = Yf[tid * 132 + c]; s += v; sq += v * v; }
        float m = s * (1.f / 128.f);
        float var = sq * (1.f / 128.f) - m * m;
        mr[tid] = m; mr[64 + tid] = rsqrtf(var + 1e-5f);
    }
    __syncthreads();
    for (int i = tid; i < 64 * 64; i += 256) {
        int p = i >> 6, q = i & 63;
        int k0 = q * 2;
        float f0 = (Yf[p * 132 + k0] - mr[p]) * mr[64 + p] * __ldg(&g2[k0]);
        float f1 = (Yf[p * 132 + k0 + 1] - mr[p]) * mr[64 + p] * __ldg(&g2[k0 + 1]);
        Yb[p * 68 + q] = pk(f0, f1);
    }
    __syncthreads();
    int wid = tid >> 5, lane = tid & 31;
    int wm = wid & 1, wn = wid >> 1;
    int gid = lane >> 2, tig = lane & 3;
    // ---- conv4 + gate -> Zb ----
    {
        float c[2][4][4];
#pragma unroll
        for (int nt = 0; nt < 4; nt++) {
            int o = wn * 16 + (nt & 1) * 8 + (nt >> 1) * 64 + 2 * tig;
            float b0 = B4[o], b1 = B4[o + 1];
#pragma unroll
            for (int mt = 0; mt < 2; mt++) {
                c[mt][nt][0] = b0; c[mt][nt][1] = b1;
                c[mt][nt][2] = b0; c[mt][nt][3] = b1;
            }
        }
#pragma unroll
        for (int kw = 0; kw < 64; kw += 8) {
            uint32_t A[2][4];
#pragma unroll
            for (int mt = 0; mt < 2; mt++) {
                int r = wm * 32 + mt * 16 + gid;
                A[mt][0] = Yb[r * 68 + kw + tig];
                A[mt][1] = Yb[(r + 8) * 68 + kw + tig];
                A[mt][2] = Yb[r * 68 + kw + 4 + tig];
                A[mt][3] = Yb[(r + 8) * 68 + kw + 4 + tig];
            }
#pragma unroll
            for (int nt = 0; nt < 4; nt++) {
                int n = wn * 16 + (nt & 1) * 8 + (nt >> 1) * 64 + gid;
                uint32_t Bf[2];
                Bf[0] = Wb[n * 68 + kw + tig];
                Bf[1] = Wb[n * 68 + kw + 4 + tig];
#pragma unroll
                for (int mt = 0; mt < 2; mt++) mma_bf16(c[mt][nt], A[mt], Bf);
            }
        }
#pragma unroll
        for (int mt = 0; mt < 2; mt++) {
            int rl = wm * 32 + mt * 16 + gid;
#pragma unroll
            for (int ntp = 0; ntp < 2; ntp++) {
                int o = wn * 16 + ntp * 8 + 2 * tig;
                Zb[rl * 36 + o / 2] =
                    pk(c[mt][ntp][0] * c[mt][ntp + 2][0], c[mt][ntp][1] * c[mt][ntp + 2][1]);
                Zb[(rl + 8) * 36 + o / 2] =
                    pk(c[mt][ntp][2] * c[mt][ntp + 2][2], c[mt][ntp][3] * c[mt][ntp + 2][3]);
            }
        }
    }
    __syncthreads();
    // ---- conv5 (K=64) + residual epilogue ----
    {
        float c[2][2][4];
#pragma unroll
        for (int nt = 0; nt < 2; nt++) {
            int o = wn * 16 + nt * 8 + 2 * tig;
            float b0 = B5[o], b1 = B5[o + 1];
#pragma unroll
            for (int mt = 0; mt < 2; mt++) {
                c[mt][nt][0] = b0; c[mt][nt][1] = b1;
                c[mt][nt][2] = b0; c[mt][nt][3] = b1;
            }
        }
#pragma unroll
        for (int kw = 0; kw < 32; kw += 8) {
            uint32_t A[2][4];
#pragma unroll
            for (int mt = 0; mt < 2; mt++) {
                int r = wm * 32 + mt * 16 + gid;
                A[mt][0] = Zb[r * 36 + kw + tig];
                A[mt][1] = Zb[(r + 8) * 36 + kw + tig];
                A[mt][2] = Zb[r * 36 + kw + 4 + tig];
                A[mt][3] = Zb[(r + 8) * 36 + kw + 4 + tig];
            }
#pragma unroll
            for (int nt = 0; nt < 2; nt++) {
                int n = wn * 16 + nt * 8 + gid;
                uint32_t Bf[2];
                Bf[0] = W5b[n * 36 + kw + tig];
                Bf[1] = W5b[n * 36 + kw + 4 + tig];
#pragma unroll
                for (int mt = 0; mt < 2; mt++) mma_bf16(c[mt][nt], A[mt], Bf);
            }
        }
        const size_t HALF = (size_t)2 * 64 * HW;
#pragma unroll
        for (int mt = 0; mt < 2; mt++) {
            int p0 = wm * 32 + mt * 16 + gid;
#pragma unroll
            for (int nt = 0; nt < 2; nt++) {
                int cc = wn * 16 + nt * 8 + 2 * tig;
                float gm0 = __ldg(&gamma[cc]), gm1 = __ldg(&gamma[cc + 1]);
#pragma unroll
                for (int rr = 0; rr < 2; rr++) {
                    int p = p0 + rr * 8;
                    float z0 = c[mt][nt][rr * 2] * gm0;
                    float z1 = c[mt][nt][rr * 2 + 1] * gm1;
                    size_t o0 = ((size_t)b * 64 + cc) * HW + pos + p;
                    size_t o1 = ((size_t)b * 64 + cc + 1) * HW + pos + p;
                    out[o0] = Yf[p * 132 + cc] + z0;
                    out[o1] = Yf[p * 132 + cc + 1] + z1;
                    out[HALF + o0] = Yf[p * 132 + 64 + cc] + z0;
                    out[HALF + o1] = Yf[p * 132 + 64 + cc + 1] + z1;
                }
            }
        }
    }
}

// ------------------------- host -------------------------
extern "C" void kernel_launch(void* const* d_in, const int* in_sizes, int n_in,
                              void* d_out, int out_size) {
    const float* x_l     = (const float*)d_in[0];
    const float* x_r     = (const float*)d_in[1];
    const float* ln1_g   = (const float*)d_in[2];
    const float* pw1_w   = (const float*)d_in[3];
    const float* pw1_b   = (const float*)d_in[4];
    const float* val_w   = (const float*)d_in[5];
    const float* val_b   = (const float*)d_in[6];
    const float* dwc_w   = (const float*)d_in[7];
    const float* dwc_b   = (const float*)d_in[8];
    const float* om_w    = (const float*)d_in[9];
    const float* om_b    = (const float*)d_in[10];
    const float* outp_w  = (const float*)d_in[11];
    const float* outp_b  = (const float*)d_in[12];
    const float* sca_w   = (const float*)d_in[13];
    const float* sca_b   = (const float*)d_in[14];
    const float* conv3_w = (const float*)d_in[15];
    const float* conv3_b = (const float*)d_in[16];
    const float* norm2_g = (const float*)d_in[17];
    const float* conv4_w = (const float*)d_in[18];
    const float* conv4_b = (const float*)d_in[19];
    const float* conv5_w = (const float*)d_in[20];
    const float* conv5_b = (const float*)d_in[21];
    const float* beta    = (const float*)d_in[22];
    const float* gamma   = (const float*)d_in[23];
    float* out = (float*)d_out;

    const int SM_LNPW1V = (64 * 68 + 128 + 64 * 36 + 128 * 36 + 128 * 68 + 64 * 68) * 4;
    const int SM_DWOM   = (2 * 128 * 68 + 9 * 128 + 128) * 4;                          // 74752
    const int SM_SOUT   = (128 * 68 + 64 * 68 + 64 * 56 + 64) * 4;                     // 66816
    const int SM_C3     = (64 * 132 + 64 * 128) * 4;
    const int SM_L245   = (64 * 132 + 64 * 68 + 128 * 68 + 64 * 36 + 64 * 36 + 128) * 4; // 104960

    cudaFuncSetAttribute(k_lnpw1v,  cudaFuncAttributeMaxDynamicSharedMemorySize, SM_LNPW1V);
    cudaFuncSetAttribute(k_dwom,    cudaFuncAttributeMaxDynamicSharedMemorySize, SM_DWOM);
    cudaFuncSetAttribute(k_souter,  cudaFuncAttributeMaxDynamicSharedMemorySize, SM_SOUT);
    cudaFuncSetAttribute(k_conv3_y, cudaFuncAttributeMaxDynamicSharedMemorySize, SM_C3);
    cudaFuncSetAttribute(k_ln2c4c5, cudaFuncAttributeMaxDynamicSharedMemorySize, SM_L245);

    k_pack    <<<296, 256>>>(pw1_w, val_w, om_w, outp_w, conv4_w, conv5_w);
    k_lnpw1v  <<<P4 / 64, 256, SM_LNPW1V>>>(x_l, x_r, ln1_g, pw1_b, val_b);
    k_dwom    <<<P4 / 128, 256, SM_DWOM>>>(dwc_w, dwc_b, om_b);
    k_souter  <<<P4 / 64, 256, SM_SOUT>>>(outp_b);
    k_sca     <<<1, 256>>>(sca_w, sca_b);
    k_conv3_y <<<P2 / 64, 256, SM_C3>>>(conv3_w, conv3_b, beta, x_l, x_r);
    k_ln2c4c5 <<<P2 / 64, 256, SM_L245>>>(norm2_g, conv4_b, conv5_b, gamma, out);
}

// round 14
// speedup vs baseline: 1.2669x; 1.2669x over previous
#include <cuda_runtime.h>
#include <cuda_bf16.h>
#include <cstdint>

#define HW 25600
#define P4 102400   // 4 images * HW  (img 0,1 = x_l b0,b1 ; img 2,3 = x_r b0,b1)
#define P2 51200    // 2 batches * HW

// ------------------------- scratch (__device__ globals) -------------------------
__device__ __nv_bfloat16 g_h[(size_t)P4 * 128];   // LN1+pw1 out, NHWC (bf16)
__device__ __nv_bfloat16 g_v[(size_t)P4 * 128];   // value proj (bf16)
__device__ __nv_bfloat16 g_om[(size_t)P4 * 112];  // offset/mask proj (bf16)
__device__ __nv_bfloat16 g_f[(size_t)P4 * 64];    // gated branch features (bf16)
__device__ float g_y[(size_t)P2 * 128];           // [y_l(64) ; y_r(64)] NHWC per batch
__device__ float g_part[256];                     // pooling sums [img][64]
__device__ float g_s[256];                        // SCA scale s[b][128]
__device__ __nv_bfloat16 g_wp[75776];             // packed bf16 weights

// packed-weight segment offsets (elements)
#define OFF_PW1   0
#define OFF_VAL   8192
#define OFF_OM    24576
#define OFF_OUTP  38912
#define OFF_C4    55296
#define OFF_C5    71680

// ------------------------- bf16 helpers -------------------------
__device__ __forceinline__ uint32_t pk(float a, float b) {
    __nv_bfloat162 t = __floats2bfloat162_rn(a, b);
    return *reinterpret_cast<uint32_t*>(&t);
}
__device__ __forceinline__ float2 upk(uint32_t u) {
    __nv_bfloat162 t = *reinterpret_cast<__nv_bfloat162*>(&u);
    return __bfloat1622float2(t);
}
__device__ __forceinline__ float4 ld4bf(const __nv_bfloat16* p) {
    uint2 u = *(const uint2*)p;
    float2 fa = upk(u.x), fb = upk(u.y);
    return make_float4(fa.x, fa.y, fb.x, fb.y);
}
__device__ __forceinline__ void mma_bf16(float* c, const uint32_t* a, const uint32_t* b) {
    asm volatile(
        "mma.sync.aligned.m16n8k16.row.col.f32.bf16.bf16.f32 "
        "{%0,%1,%2,%3}, {%4,%5,%6,%7}, {%8,%9}, {%0,%1,%2,%3};"
        : "+f"(c[0]), "+f"(c[1]), "+f"(c[2]), "+f"(c[3])
        : "r"(a[0]), "r"(a[1]), "r"(a[2]), "r"(a[3]), "r"(b[0]), "r"(b[1]));
}
__device__ __forceinline__ void fma8(float* a, float w, uint4 u) {
    float2 f0 = upk(u.x), f1 = upk(u.y), f2 = upk(u.z), f3 = upk(u.w);
    a[0] += w * f0.x; a[1] += w * f0.y; a[2] += w * f1.x; a[3] += w * f1.y;
    a[4] += w * f2.x; a[5] += w * f2.y; a[6] += w * f3.x; a[7] += w * f3.y;
}

// ------------------------- weight pack + g_part zero -------------------------
__global__ void __launch_bounds__(256) k_pack(const float* __restrict__ pw1,
                                              const float* __restrict__ val,
                                              const float* __restrict__ om,
                                              const float* __restrict__ outp,
                                              const float* __restrict__ c4,
                                              const float* __restrict__ c5) {
    int i = blockIdx.x * 256 + threadIdx.x;
    if (blockIdx.x == 0) g_part[threadIdx.x] = 0.f;
    if (i >= 75776) return;
    float v;
    if (i < OFF_VAL)       v = pw1[i - OFF_PW1];
    else if (i < OFF_OM)   v = val[i - OFF_VAL];
    else if (i < OFF_OUTP) v = om[i - OFF_OM];
    else if (i < OFF_C4)   v = outp[i - OFF_OUTP];
    else if (i < OFF_C5)   v = c4[i - OFF_C4];
    else                   v = c5[i - OFF_C5];
    g_wp[i] = __float2bfloat16_rn(v);
}

// ------------------------- kernel 1: LN + pw1 + val GEMM fused -------------------------
__global__ void __launch_bounds__(256) k_lnpw1v(const float* __restrict__ x_l,
                                                const float* __restrict__ x_r,
                                                const float* __restrict__ g1,
                                                const float* __restrict__ B1,
                                                const float* __restrict__ Bv) {
    extern __shared__ float sm[];
    float* Xf = sm;                            // 64*68 fp32
    float* mr = Xf + 64 * 68;                  // 128
    uint32_t* Xb = (uint32_t*)(mr + 128);      // 64*36 (bf16 pairs, K=64)
    uint32_t* Wb = Xb + 64 * 36;               // 128*36 (pw1 weights)
    uint32_t* Wv = Wb + 128 * 36;              // 128*68 (val weights, K=128)
    uint32_t* Hb = Wv + 128 * 68;              // 64*68  (h tile bf16)
    int tid = threadIdx.x;
    int base = blockIdx.x * 64;
    int img = base / HW;
    int pos = base - img * HW;
    const float* xp = (img < 2) ? (x_l + (size_t)img * HW * 64)
                                : (x_r + (size_t)(img - 2) * HW * 64);
    for (int i = tid; i < 64 * 64; i += 256) {
        int c = i >> 6, p = i & 63;
        Xf[p * 68 + c] = xp[(size_t)c * HW + pos + p];
    }
    const uint4* Wp1 = (const uint4*)(g_wp + OFF_PW1);
    for (int i = tid; i < 1024; i += 256) {
        int row = i >> 3, q = i & 7;
        uint4 u = __ldg(&Wp1[row * 8 + q]);
        Wb[row * 36 + q * 4]     = u.x;
        Wb[row * 36 + q * 4 + 1] = u.y;
        Wb[row * 36 + q * 4 + 2] = u.z;
        Wb[row * 36 + q * 4 + 3] = u.w;
    }
    const uint4* Wpv = (const uint4*)(g_wp + OFF_VAL);
    for (int i = tid; i < 2048; i += 256) {
        int row = i >> 4, q = i & 15;
        uint4 u = __ldg(&Wpv[row * 16 + q]);
        Wv[row * 68 + q * 4]     = u.x;
        Wv[row * 68 + q * 4 + 1] = u.y;
        Wv[row * 68 + q * 4 + 2] = u.z;
        Wv[row * 68 + q * 4 + 3] = u.w;
    }
    __syncthreads();
    if (tid < 64) {
        float s = 0.f, sq = 0.f;
        for (int c = 0; c < 64; c++) { float v = Xf[tid * 68 + c]; s += v; sq += v * v; }
        float m = s * (1.f / 64.f);
        float var = sq * (1.f / 64.f) - m * m;
        mr[tid] = m; mr[64 + tid] = rsqrtf(var + 1e-5f);
    }
    __syncthreads();
    for (int i = tid; i < 64 * 32; i += 256) {
        int p = i >> 5, q = i & 31;
        int k0 = q * 2;
        float f0 = (Xf[p * 68 + k0] - mr[p]) * mr[64 + p] * __ldg(&g1[k0]);
        float f1 = (Xf[p * 68 + k0 + 1] - mr[p]) * mr[64 + p] * __ldg(&g1[k0 + 1]);
        Xb[p * 36 + q] = pk(f0, f1);
    }
    __syncthreads();
    int wid = tid >> 5, lane = tid & 31;
    int wm = wid & 1, wn = wid >> 1;
    int gid = lane >> 2, tig = lane & 3;
    // ---- phase 1: h ----
    {
        float c[2][4][4];
#pragma unroll
        for (int nt = 0; nt < 4; nt++) {
            int o = wn * 32 + nt * 8 + 2 * tig;
            float b0 = B1[o], b1 = B1[o + 1];
#pragma unroll
            for (int mt = 0; mt < 2; mt++) {
                c[mt][nt][0] = b0; c[mt][nt][1] = b1;
                c[mt][nt][2] = b0; c[mt][nt][3] = b1;
            }
        }
#pragma unroll
        for (int kw = 0; kw < 32; kw += 8) {
            uint32_t A[2][4];
#pragma unroll
            for (int mt = 0; mt < 2; mt++) {
                int r = wm * 32 + mt * 16 + gid;
                A[mt][0] = Xb[r * 36 + kw + tig];
                A[mt][1] = Xb[(r + 8) * 36 + kw + tig];
                A[mt][2] = Xb[r * 36 + kw + 4 + tig];
                A[mt][3] = Xb[(r + 8) * 36 + kw + 4 + tig];
            }
#pragma unroll
            for (int nt = 0; nt < 4; nt++) {
                int n = wn * 32 + nt * 8 + gid;
                uint32_t Bf[2];
                Bf[0] = Wb[n * 36 + kw + tig];
                Bf[1] = Wb[n * 36 + kw + 4 + tig];
#pragma unroll
                for (int mt = 0; mt < 2; mt++) mma_bf16(c[mt][nt], A[mt], Bf);
            }
        }
        uint32_t* gh = (uint32_t*)g_h;
#pragma unroll
        for (int mt = 0; mt < 2; mt++) {
            int rl = wm * 32 + mt * 16 + gid;
            size_t r0 = base + rl;
#pragma unroll
            for (int nt = 0; nt < 4; nt++) {
                int o = wn * 32 + nt * 8 + 2 * tig;
                uint32_t w0 = pk(c[mt][nt][0], c[mt][nt][1]);
                uint32_t w1 = pk(c[mt][nt][2], c[mt][nt][3]);
                gh[r0 * 64 + o / 2] = w0;
                gh[(r0 + 8) * 64 + o / 2] = w1;
                Hb[rl * 68 + o / 2] = w0;
                Hb[(rl + 8) * 68 + o / 2] = w1;
            }
        }
    }
    __syncthreads();
    // ---- phase 2: v ----
    {
        float c[2][4][4];
#pragma unroll
        for (int nt = 0; nt < 4; nt++) {
            int o = wn * 32 + nt * 8 + 2 * tig;
            float b0 = Bv[o], b1 = Bv[o + 1];
#pragma unroll
            for (int mt = 0; mt < 2; mt++) {
                c[mt][nt][0] = b0; c[mt][nt][1] = b1;
                c[mt][nt][2] = b0; c[mt][nt][3] = b1;
            }
        }
#pragma unroll
        for (int kw = 0; kw < 64; kw += 8) {
            uint32_t A[2][4];
#pragma unroll
            for (int mt = 0; mt < 2; mt++) {
                int r = wm * 32 + mt * 16 + gid;
                A[mt][0] = Hb[r * 68 + kw + tig];
                A[mt][1] = Hb[(r + 8) * 68 + kw + tig];
                A[mt][2] = Hb[r * 68 + kw + 4 + tig];
                A[mt][3] = Hb[(r + 8) * 68 + kw + 4 + tig];
            }
#pragma unroll
            for (int nt = 0; nt < 4; nt++) {
                int n = wn * 32 + nt * 8 + gid;
                uint32_t Bf[2];
                Bf[0] = Wv[n * 68 + kw + tig];
                Bf[1] = Wv[n * 68 + kw + 4 + tig];
#pragma unroll
                for (int mt = 0; mt < 2; mt++) mma_bf16(c[mt][nt], A[mt], Bf);
            }
        }
        uint32_t* gv = (uint32_t*)g_v;
#pragma unroll
        for (int mt = 0; mt < 2; mt++) {
            size_t r0 = base + wm * 32 + mt * 16 + gid;
#pragma unroll
            for (int nt = 0; nt < 4; nt++) {
                int o = wn * 32 + nt * 8 + 2 * tig;
                gv[r0 * 64 + o / 2] = pk(c[mt][nt][0], c[mt][nt][1]);
                gv[(r0 + 8) * 64 + o / 2] = pk(c[mt][nt][2], c[mt][nt][3]);
            }
        }
    }
}

// ------------------------- fused: depthwise 3x3 + om GEMM (128px x 112, K=128) -------------------------
__global__ void __launch_bounds__(256) k_dwom(const float* __restrict__ Wd,
                                              const float* __restrict__ Bd,
                                              const float* __restrict__ Bb) {
    const int N = 112;
    extern __shared__ uint32_t smu[];
    uint32_t* Xu = smu;                        // 128*68 words (dwc out, bf16)
    uint32_t* Wu = smu + 128 * 68;             // 128*68 words (om weights)
    float* wts = (float*)(Wu + 128 * 68);      // 9*128 dwc weights
    float* bds = wts + 9 * 128;                // 128 dwc bias
    int tid = threadIdx.x;
    size_t base = (size_t)blockIdx.x * 128;
    int img = (int)(base / HW);
    int pbase = (int)(base - (size_t)img * HW);
    for (int i = tid; i < 9 * 128; i += 256) wts[i] = __ldg(&Wd[i]);
    if (tid < 128) bds[tid] = __ldg(&Bd[tid]);
    const uint4* Wg = (const uint4*)(g_wp + OFF_OM);
    for (int i = tid; i < 2048; i += 256) {
        int row = i >> 4, q = i & 15;
        uint4 u = make_uint4(0u, 0u, 0u, 0u);
        if (row < N) u = __ldg(&Wg[row * 16 + q]);
        Wu[row * 68 + q * 4]     = u.x;
        Wu[row * 68 + q * 4 + 1] = u.y;
        Wu[row * 68 + q * 4 + 2] = u.z;
        Wu[row * 68 + q * 4 + 3] = u.w;
    }
    __syncthreads();
    const __nv_bfloat16* hb = g_h + (size_t)img * HW * 128;
    for (int it = tid; it < 4096; it += 256) {
        int px = it >> 5;
        int wg = it & 31;
        int c0 = wg * 4;
        int pos = pbase + px;
        int hh = pos / 160, ww = pos - hh * 160;
        float a0 = bds[c0], a1 = bds[c0 + 1], a2 = bds[c0 + 2], a3 = bds[c0 + 3];
#pragma unroll
        for (int dy = 0; dy < 3; dy++) {
            int y = hh + dy - 1;
            if ((unsigned)y >= 160u) continue;
            const __nv_bfloat16* rowp = hb + ((size_t)y * 160) * 128 + c0;
#pragma unroll
            for (int dx = 0; dx < 3; dx++) {
                int x = ww + dx - 1;
                if ((unsigned)x >= 160u) continue;
                float4 v = ld4bf(&rowp[(size_t)x * 128]);
                float4 wv = *(const float4*)&wts[(dy * 3 + dx) * 128 + c0];
                a0 += v.x * wv.x; a1 += v.y * wv.y; a2 += v.z * wv.z; a3 += v.w * wv.w;
            }
        }
        Xu[px * 68 + wg * 2]     = pk(a0, a1);
        Xu[px * 68 + wg * 2 + 1] = pk(a2, a3);
    }
    __syncthreads();
    int wid = tid >> 5, lane = tid & 31;
    int wm = wid & 3, wn = wid >> 2;
    int gid = lane >> 2, tig = lane & 3;
    float c[2][8][4];
#pragma unroll
    for (int nt = 0; nt < 8; nt++) {
        int o = wn * 64 + nt * 8 + 2 * tig;
        float b0 = (o < N) ? Bb[o] : 0.f;
        float b1 = (o + 1 < N) ? Bb[o + 1] : 0.f;
#pragma unroll
        for (int mt = 0; mt < 2; mt++) {
            c[mt][nt][0] = b0; c[mt][nt][1] = b1;
            c[mt][nt][2] = b0; c[mt][nt][3] = b1;
        }
    }
#pragma unroll
    for (int kw = 0; kw < 64; kw += 8) {
        uint32_t A[2][4];
#pragma unroll
        for (int mt = 0; mt < 2; mt++) {
            int r = wm * 32 + mt * 16 + gid;
            A[mt][0] = Xu[r * 68 + kw + tig];
            A[mt][1] = Xu[(r + 8) * 68 + kw + tig];
            A[mt][2] = Xu[r * 68 + kw + 4 + tig];
            A[mt][3] = Xu[(r + 8) * 68 + kw + 4 + tig];
        }
        uint32_t Bf[8][2];
#pragma unroll
        for (int nt = 0; nt < 8; nt++) {
            int n = wn * 64 + nt * 8 + gid;
            Bf[nt][0] = Wu[n * 68 + kw + tig];
            Bf[nt][1] = Wu[n * 68 + kw + 4 + tig];
        }
#pragma unroll
        for (int mt = 0; mt < 2; mt++)
#pragma unroll
            for (int nt = 0; nt < 8; nt++)
                mma_bf16(c[mt][nt], A[mt], Bf[nt]);
    }
    uint32_t* Yu = (uint32_t*)g_om;
#pragma unroll
    for (int mt = 0; mt < 2; mt++) {
        size_t r0 = base + wm * 32 + mt * 16 + gid;
#pragma unroll
        for (int nt = 0; nt < 8; nt++) {
            int o = wn * 64 + nt * 8 + 2 * tig;
            if (o < N) {
                Yu[r0 * 56 + o / 2] = pk(c[mt][nt][0], c[mt][nt][1]);
                Yu[(r0 + 8) * 56 + o / 2] = pk(c[mt][nt][2], c[mt][nt][3]);
            }
        }
    }
}

// ------------------------- fused: deform sample + outp GEMM + gate + pool partial -------------------------
// smem layout: Xb [0,4352) | OMt/Wb overlay [4352,13056) | pacc [13056,13120)
__global__ void __launch_bounds__(256) k_souter(const float* __restrict__ Bo) {
    extern __shared__ uint32_t smu[];
    uint32_t* Xb = smu;                         // 64*68 words (sampled bf16)
    uint32_t* OMt = smu + 4352;                 // 64*56 words (om tile, phase 1)
    uint32_t* Wb = smu + 4352;                  // 128*68 words (outp weights, phase 2 overlay)
    float* pacc = (float*)(smu + 13056);        // 64 floats
    int tid = threadIdx.x;
    int base = blockIdx.x * 64;
    int img = base / HW;
    int pbase = base - img * HW;
    if (tid < 64) pacc[tid] = 0.f;
    // stage om tile (coalesced)
    {
        const uint32_t* oms = (const uint32_t*)g_om + ((size_t)img * HW + pbase) * 56;
        for (int i = tid; i < 3584; i += 256) OMt[i] = __ldg(&oms[i]);
    }
    __syncthreads();
    // ---- sampling: warp = 8 px (2 at a time); lane = (pxh, g, c8) -> 8 channels ----
    int wrp = tid >> 5, lane = tid & 31;
    int pxh = lane >> 4;
    int g = (lane >> 2) & 3;
    int c8 = lane & 3;
    const uint4* vp = (const uint4*)(g_v + (size_t)img * HW * 128 + g * 32 + c8 * 8);
    for (int pp = 0; pp < 4; pp++) {
        int px = wrp * 8 + pp * 2 + pxh;
        int pos = pbase + px;
        int hh = pos / 160, ww = pos - hh * 160;
        const uint32_t* omp = OMt + px * 56;
        float a[8] = {0.f, 0.f, 0.f, 0.f, 0.f, 0.f, 0.f, 0.f};
#pragma unroll
        for (int k = 0; k < 9; k++) {
            int w0i = (g * 27 + 3 * k) >> 1;
            float2 f0 = upk(omp[w0i]);
            float2 f1 = upk(omp[w0i + 1]);
            bool odd = ((g + k) & 1);
            float ox = odd ? f0.y : f0.x;
            float oy = odd ? f1.x : f0.y;
            float mk = odd ? f1.y : f1.x;
            float fx = (float)(ww + (k % 3) - 1) + ox;
            float fy = (float)(hh + (k / 3) - 1) + oy;
            float x0f = floorf(fx), y0f = floorf(fy);
            float tx = fx - x0f, ty = fy - y0f;
            int ix = (int)x0f, iy = (int)y0f;
            bool vx0 = (unsigned)ix < 160u, vx1 = (unsigned)(ix + 1) < 160u;
            bool vy0 = (unsigned)iy < 160u, vy1 = (unsigned)(iy + 1) < 160u;
            float w00 = (vx0 && vy0) ? (1.f - tx) * (1.f - ty) * mk : 0.f;
            float w01 = (vx1 && vy0) ? tx * (1.f - ty) * mk : 0.f;
            float w10 = (vx0 && vy1) ? (1.f - tx) * ty * mk : 0.f;
            float w11 = (vx1 && vy1) ? tx * ty * mk : 0.f;
            int ix0 = min(max(ix, 0), 159), ix1 = min(max(ix + 1, 0), 159);
            int iy0 = min(max(iy, 0), 159), iy1 = min(max(iy + 1, 0), 159);
            int r0 = iy0 * 160, r1 = iy1 * 160;
            fma8(a, w00, __ldg(&vp[(r0 + ix0) * 16]));
            fma8(a, w01, __ldg(&vp[(r0 + ix1) * 16]));
            fma8(a, w10, __ldg(&vp[(r1 + ix0) * 16]));
            fma8(a, w11, __ldg(&vp[(r1 + ix1) * 16]));
        }
        int cw = g * 16 + c8 * 4;   // channel word base within row
#pragma unroll
        for (int j = 0; j < 4; j++)
            Xb[px * 68 + cw + j] = pk(a[2 * j], a[2 * j + 1]);
    }
    __syncthreads();
    // load outp weights (overlays OMt)
    const uint4* Wg = (const uint4*)(g_wp + OFF_OUTP);
    for (int i = tid; i < 2048; i += 256) {
        int row = i >> 4, q = i & 15;
        uint4 u = __ldg(&Wg[row * 16 + q]);
        Wb[row * 68 + q * 4]     = u.x;
        Wb[row * 68 + q * 4 + 1] = u.y;
        Wb[row * 68 + q * 4 + 2] = u.z;
        Wb[row * 68 + q * 4 + 3] = u.w;
    }
    __syncthreads();
    // ---- GEMM + gate + pool partial ----
    int wm = wrp & 1, wn = wrp >> 1;
    int gid = lane >> 2, tig = lane & 3;
    float c[2][4][4];
#pragma unroll
    for (int nt = 0; nt < 4; nt++) {
        int o = wn * 16 + (nt & 1) * 8 + (nt >> 1) * 64 + 2 * tig;
        float b0 = Bo[o], b1 = Bo[o + 1];
#pragma unroll
        for (int mt = 0; mt < 2; mt++) {
            c[mt][nt][0] = b0; c[mt][nt][1] = b1;
            c[mt][nt][2] = b0; c[mt][nt][3] = b1;
        }
    }
#pragma unroll
    for (int kw = 0; kw < 64; kw += 8) {
        uint32_t A[2][4];
#pragma unroll
        for (int mt = 0; mt < 2; mt++) {
            int r = wm * 32 + mt * 16 + gid;
            A[mt][0] = Xb[r * 68 + kw + tig];
            A[mt][1] = Xb[(r + 8) * 68 + kw + tig];
            A[mt][2] = Xb[r * 68 + kw + 4 + tig];
            A[mt][3] = Xb[(r + 8) * 68 + kw + 4 + tig];
        }
#pragma unroll
        for (int nt = 0; nt < 4; nt++) {
            int n = wn * 16 + (nt & 1) * 8 + (nt >> 1) * 64 + gid;
            uint32_t Bf[2];
            Bf[0] = Wb[n * 68 + kw + tig];
            Bf[1] = Wb[n * 68 + kw + 4 + tig];
#pragma unroll
            for (int mt = 0; mt < 2; mt++) mma_bf16(c[mt][nt], A[mt], Bf);
        }
    }
    uint32_t* gf = (uint32_t*)g_f;
#pragma unroll
    for (int ntp = 0; ntp < 2; ntp++) {
        int o = wn * 16 + ntp * 8 + 2 * tig;
        float s0 = 0.f, s1 = 0.f;
#pragma unroll
        for (int mt = 0; mt < 2; mt++) {
            size_t r0 = base + wm * 32 + mt * 16 + gid;
            float p00 = c[mt][ntp][0] * c[mt][ntp + 2][0];
            float p01 = c[mt][ntp][1] * c[mt][ntp + 2][1];
            float p10 = c[mt][ntp][2] * c[mt][ntp + 2][2];
            float p11 = c[mt][ntp][3] * c[mt][ntp + 2][3];
            gf[r0 * 32 + o / 2] = pk(p00, p01);
            gf[(r0 + 8) * 32 + o / 2] = pk(p10, p11);
            s0 += p00 + p10;
            s1 += p01 + p11;
        }
        atomicAdd(&pacc[o], s0);
        atomicAdd(&pacc[o + 1], s1);
    }
    __syncthreads();
    if (tid < 64) atomicAdd(&g_part[img * 64 + tid], pacc[tid]);
}

// ------------------------- finish pooling + SCA projection -------------------------
__global__ void __launch_bounds__(256) k_sca(const float* __restrict__ sw, const float* __restrict__ sb) {
    __shared__ float shp[256];
    int tid = threadIdx.x;
    int b = tid >> 7, c = tid & 127;
    int img = (c < 64) ? b : (2 + b);
    int cc = c & 63;
    shp[tid] = g_part[img * 64 + cc] * (1.f / (float)HW);
    __syncthreads();
    float acc = __ldg(&sb[c]);
    for (int k = 0; k < 128; k++) acc += shp[b * 128 + k] * __ldg(&sw[c * 128 + k]);
    g_s[tid] = acc;
}

// ------------------------- SCA-folded conv3 + dual residual -> g_y -------------------------
__global__ void __launch_bounds__(256) k_conv3_y(const float* __restrict__ W3,
                                                 const float* __restrict__ B3,
                                                 const float* __restrict__ beta,
                                                 const float* __restrict__ x_l,
                                                 const float* __restrict__ x_r) {
    extern __shared__ float sm[];
    float* Fs = sm;              // 64*132
    float* W3s = sm + 64 * 132;  // 64*128 (scale-folded)
    int tid = threadIdx.x;
    int base = blockIdx.x * 64;
    int b = base / HW;
    int pos = base - b * HW;
    const uint32_t* gf = (const uint32_t*)g_f;
    for (int i = tid; i < 64 * 64; i += 256) {
        int p = i >> 6, w = i & 63;
        int imgX = (w < 32) ? b : (2 + b);
        float2 f = upk(gf[((size_t)imgX * HW + pos + p) * 32 + (w & 31)]);
        Fs[p * 132 + 2 * w] = f.x;
        Fs[p * 132 + 2 * w + 1] = f.y;
    }
    for (int i = tid; i < 64 * 128; i += 256) {
        int o = i & 127;
        W3s[i] = W3[i] * g_s[b * 128 + o];
    }
    __syncthreads();
    int pr = tid & 15, og = tid >> 4;
    float acc[4][4];
#pragma unroll
    for (int j = 0; j < 4; j++) {
        float bv = B3[og * 4 + j];
#pragma unroll
        for (int i = 0; i < 4; i++) acc[i][j] = bv;
    }
#pragma unroll 4
    for (int k = 0; k < 128; k += 4) {
        float4 xv[4];
#pragma unroll
        for (int i = 0; i < 4; i++) xv[i] = *(const float4*)&Fs[(pr + 16 * i) * 132 + k];
#pragma unroll
        for (int j = 0; j < 4; j++) {
            float4 wv = *(const float4*)&W3s[(og * 4 + j) * 128 + k];
#pragma unroll
            for (int i = 0; i < 4; i++)
                acc[i][j] += xv[i].x * wv.x + xv[i].y * wv.y + xv[i].z * wv.z + xv[i].w * wv.w;
        }
    }
#pragma unroll
    for (int i = 0; i < 4; i++) {
        int p = pr + 16 * i;
#pragma unroll
        for (int j = 0; j < 4; j++) {
            int jj = og * 4 + j;
            float bt = __ldg(&beta[jj]);
            float x3 = acc[i][j] * bt;
            float xl = x_l[((size_t)b * 64 + jj) * HW + pos + p];
            float xr = x_r[((size_t)b * 64 + jj) * HW + pos + p];
            g_y[(size_t)(base + p) * 128 + jj] = xl + x3;
            g_y[(size_t)(base + p) * 128 + 64 + jj] = xr + x3;
        }
    }
}

// ------------------------- LN2 + conv4 + gate + conv5 + final residuals -> out -------------------------
__global__ void __launch_bounds__(256) k_ln2c4c5(const float* __restrict__ g2,
                                                 const float* __restrict__ B4,
                                                 const float* __restrict__ B5,
                                                 const float* __restrict__ gamma,
                                                 float* __restrict__ out) {
    extern __shared__ float sm[];
    float* Yf = sm;                                 // 64*132 fp32
    uint32_t* Yb = (uint32_t*)(sm + 64 * 132);      // 64*68 words
    uint32_t* Wb = Yb + 64 * 68;                    // 128*68 words (conv4)
    uint32_t* Zb = Wb + 128 * 68;                   // 64*36 words (zg bf16)
    uint32_t* W5b = Zb + 64 * 36;                   // 64*36 words (conv5)
    float* mr = (float*)(W5b + 64 * 36);            // 128
    int tid = threadIdx.x;
    int base = blockIdx.x * 64;
    int b = base / HW;
    int pos = base - b * HW;
    for (int i = tid; i < 64 * 128; i += 256) {
        int p = i >> 7, c = i & 127;
        Yf[p * 132 + c] = g_y[(size_t)(base + p) * 128 + c];
    }
    const uint4* Wg = (const uint4*)(g_wp + OFF_C4);
    for (int i = tid; i < 2048; i += 256) {
        int row = i >> 4, q = i & 15;
        uint4 u = __ldg(&Wg[row * 16 + q]);
        Wb[row * 68 + q * 4]     = u.x;
        Wb[row * 68 + q * 4 + 1] = u.y;
        Wb[row * 68 + q * 4 + 2] = u.z;
        Wb[row * 68 + q * 4 + 3] = u.w;
    }
    const uint4* W5g = (const uint4*)(g_wp + OFF_C5);
    for (int i = tid; i < 512; i += 256) {
        int row = i >> 3, q = i & 7;
        uint4 u = __ldg(&W5g[row * 8 + q]);
        W5b[row * 36 + q * 4]     = u.x;
        W5b[row * 36 + q * 4 + 1] = u.y;
        W5b[row * 36 + q * 4 + 2] = u.z;
        W5b[row * 36 + q * 4 + 3] = u.w;
    }
    __syncthreads();
    if (tid < 64) {
        float s = 0.f, sq = 0.f;
        for (int c = 0; c < 128; c++) { float v = Yf[tid * 132 + c]; s += v; sq += v * v; }
        float m = s * (1.f / 128.f);
        float var = sq * (1.f / 128.f) - m * m;
        mr[tid] = m; mr[64 + tid] = rsqrtf(var + 1e-5f);
    }
    __syncthreads();
    for (int i = tid; i < 64 * 64; i += 256) {
        int p = i >> 6, q = i & 63;
        int k0 = q * 2;
        float f0 = (Yf[p * 132 + k0] - mr[p]) * mr[64 + p] * __ldg(&g2[k0]);
        float f1 = (Yf[p * 132 + k0 + 1] - mr[p]) * mr[64 + p] * __ldg(&g2[k0 + 1]);
        Yb[p * 68 + q] = pk(f0, f1);
    }
    __syncthreads();
    int wid = tid >> 5, lane = tid & 31;
    int wm = wid & 1, wn = wid >> 1;
    int gid = lane >> 2, tig = lane & 3;
    // ---- conv4 + gate -> Zb ----
    {
        float c[2][4][4];
#pragma unroll
        for (int nt = 0; nt < 4; nt++) {
            int o = wn * 16 + (nt & 1) * 8 + (nt >> 1) * 64 + 2 * tig;
            float b0 = B4[o], b1 = B4[o + 1];
#pragma unroll
            for (int mt = 0; mt < 2; mt++) {
                c[mt][nt][0] = b0; c[mt][nt][1] = b1;
                c[mt][nt][2] = b0; c[mt][nt][3] = b1;
            }
        }
#pragma unroll
        for (int kw = 0; kw < 64; kw += 8) {
            uint32_t A[2][4];
#pragma unroll
            for (int mt = 0; mt < 2; mt++) {
                int r = wm * 32 + mt * 16 + gid;
                A[mt][0] = Yb[r * 68 + kw + tig];
                A[mt][1] = Yb[(r + 8) * 68 + kw + tig];
                A[mt][2] = Yb[r * 68 + kw + 4 + tig];
                A[mt][3] = Yb[(r + 8) * 68 + kw + 4 + tig];
            }
#pragma unroll
            for (int nt = 0; nt < 4; nt++) {
                int n = wn * 16 + (nt & 1) * 8 + (nt >> 1) * 64 + gid;
                uint32_t Bf[2];
                Bf[0] = Wb[n * 68 + kw + tig];
                Bf[1] = Wb[n * 68 + kw + 4 + tig];
#pragma unroll
                for (int mt = 0; mt < 2; mt++) mma_bf16(c[mt][nt], A[mt], Bf);
            }
        }
#pragma unroll
        for (int mt = 0; mt < 2; mt++) {
            int rl = wm * 32 + mt * 16 + gid;
#pragma unroll
            for (int ntp = 0; ntp < 2; ntp++) {
                int o = wn * 16 + ntp * 8 + 2 * tig;
                Zb[rl * 36 + o / 2] =
                    pk(c[mt][ntp][0] * c[mt][ntp + 2][0], c[mt][ntp][1] * c[mt][ntp + 2][1]);
                Zb[(rl + 8) * 36 + o / 2] =
                    pk(c[mt][ntp][2] * c[mt][ntp + 2][2], c[mt][ntp][3] * c[mt][ntp + 2][3]);
            }
        }
    }
    __syncthreads();
    // ---- conv5 (K=64) + residual epilogue ----
    {
        float c[2][2][4];
#pragma unroll
        for (int nt = 0; nt < 2; nt++) {
            int o = wn * 16 + nt * 8 + 2 * tig;
            float b0 = B5[o], b1 = B5[o + 1];
#pragma unroll
            for (int mt = 0; mt < 2; mt++) {
                c[mt][nt][0] = b0; c[mt][nt][1] = b1;
                c[mt][nt][2] = b0; c[mt][nt][3] = b1;
            }
        }
#pragma unroll
        for (int kw = 0; kw < 32; kw += 8) {
            uint32_t A[2][4];
#pragma unroll
            for (int mt = 0; mt < 2; mt++) {
                int r = wm * 32 + mt * 16 + gid;
                A[mt][0] = Zb[r * 36 + kw + tig];
                A[mt][1] = Zb[(r + 8) * 36 + kw + tig];
                A[mt][2] = Zb[r * 36 + kw + 4 + tig];
                A[mt][3] = Zb[(r + 8) * 36 + kw + 4 + tig];
            }
#pragma unroll
            for (int nt = 0; nt < 2; nt++) {
                int n = wn * 16 + nt * 8 + gid;
                uint32_t Bf[2];
                Bf[0] = W5b[n * 36 + kw + tig];
                Bf[1] = W5b[n * 36 + kw + 4 + tig];
#pragma unroll
                for (int mt = 0; mt < 2; mt++) mma_bf16(c[mt][nt], A[mt], Bf);
            }
        }
        const size_t HALF = (size_t)2 * 64 * HW;
#pragma unroll
        for (int mt = 0; mt < 2; mt++) {
            int p0 = wm * 32 + mt * 16 + gid;
#pragma unroll
            for (int nt = 0; nt < 2; nt++) {
                int cc = wn * 16 + nt * 8 + 2 * tig;
                float gm0 = __ldg(&gamma[cc]), gm1 = __ldg(&gamma[cc + 1]);
#pragma unroll
                for (int rr = 0; rr < 2; rr++) {
                    int p = p0 + rr * 8;
                    float z0 = c[mt][nt][rr * 2] * gm0;
                    float z1 = c[mt][nt][rr * 2 + 1] * gm1;
                    size_t o0 = ((size_t)b * 64 + cc) * HW + pos + p;
                    size_t o1 = ((size_t)b * 64 + cc + 1) * HW + pos + p;
                    out[o0] = Yf[p * 132 + cc] + z0;
                    out[o1] = Yf[p * 132 + cc + 1] + z1;
                    out[HALF + o0] = Yf[p * 132 + 64 + cc] + z0;
                    out[HALF + o1] = Yf[p * 132 + 64 + cc + 1] + z1;
                }
            }
        }
    }
}

// ------------------------- host -------------------------
extern "C" void kernel_launch(void* const* d_in, const int* in_sizes, int n_in,
                              void* d_out, int out_size) {
    const float* x_l     = (const float*)d_in[0];
    const float* x_r     = (const float*)d_in[1];
    const float* ln1_g   = (const float*)d_in[2];
    const float* pw1_w   = (const float*)d_in[3];
    const float* pw1_b   = (const float*)d_in[4];
    const float* val_w   = (const float*)d_in[5];
    const float* val_b   = (const float*)d_in[6];
    const float* dwc_w   = (const float*)d_in[7];
    const float* dwc_b   = (const float*)d_in[8];
    const float* om_w    = (const float*)d_in[9];
    const float* om_b    = (const float*)d_in[10];
    const float* outp_w  = (const float*)d_in[11];
    const float* outp_b  = (const float*)d_in[12];
    const float* sca_w   = (const float*)d_in[13];
    const float* sca_b   = (const float*)d_in[14];
    const float* conv3_w = (const float*)d_in[15];
    const float* conv3_b = (const float*)d_in[16];
    const float* norm2_g = (const float*)d_in[17];
    const float* conv4_w = (const float*)d_in[18];
    const float* conv4_b = (const float*)d_in[19];
    const float* conv5_w = (const float*)d_in[20];
    const float* conv5_b = (const float*)d_in[21];
    const float* beta    = (const float*)d_in[22];
    const float* gamma   = (const float*)d_in[23];
    float* out = (float*)d_out;

    const int SM_LNPW1V = (64 * 68 + 128 + 64 * 36 + 128 * 36 + 128 * 68 + 64 * 68) * 4;
    const int SM_DWOM   = (2 * 128 * 68 + 9 * 128 + 128) * 4;
    const int SM_SOUT   = 13120 * 4;                                                   // 52480
    const int SM_C3     = (64 * 132 + 64 * 128) * 4;
    const int SM_L245   = (64 * 132 + 64 * 68 + 128 * 68 + 64 * 36 + 64 * 36 + 128) * 4;

    cudaFuncSetAttribute(k_lnpw1v,  cudaFuncAttributeMaxDynamicSharedMemorySize, SM_LNPW1V);
    cudaFuncSetAttribute(k_dwom,    cudaFuncAttributeMaxDynamicSharedMemorySize, SM_DWOM);
    cudaFuncSetAttribute(k_souter,  cudaFuncAttributeMaxDynamicSharedMemorySize, SM_SOUT);
    cudaFuncSetAttribute(k_conv3_y, cudaFuncAttributeMaxDynamicSharedMemorySize, SM_C3);
    cudaFuncSetAttribute(k_ln2c4c5, cudaFuncAttributeMaxDynamicSharedMemorySize, SM_L245);

    k_pack    <<<296, 256>>>(pw1_w, val_w, om_w, outp_w, conv4_w, conv5_w);
    k_lnpw1v  <<<P4 / 64, 256, SM_LNPW1V>>>(x_l, x_r, ln1_g, pw1_b, val_b);
    k_dwom    <<<P4 / 128, 256, SM_DWOM>>>(dwc_w, dwc_b, om_b);
    k_souter  <<<P4 / 64, 256, SM_SOUT>>>(outp_b);
    k_sca     <<<1, 256>>>(sca_w, sca_b);
    k_conv3_y <<<P2 / 64, 256, SM_C3>>>(conv3_w, conv3_b, beta, x_l, x_r);
    k_ln2c4c5 <<<P2 / 64, 256, SM_L245>>>(norm2_g, conv4_b, conv5_b, gamma, out);
}

// round 17
// speedup vs baseline: 1.2891x; 1.0175x over previous
#include <cuda_runtime.h>
#include <cuda_bf16.h>
#include <cstdint>

#define HW 25600
#define P4 102400   // 4 images * HW  (img 0,1 = x_l b0,b1 ; img 2,3 = x_r b0,b1)
#define P2 51200    // 2 batches * HW
#define PW 168      // padded width/height for v (4-px zero border)
#define PA 28224    // PW*PW

// ------------------------- scratch (__device__ globals) -------------------------
__device__ __nv_bfloat16 g_h[(size_t)P4 * 128];       // LN1+pw1 out, NHWC (bf16)
__device__ __nv_bfloat16 g_vp[(size_t)4 * PA * 128];  // value proj, zero-padded (bf16)
__device__ __nv_bfloat16 g_om[(size_t)P4 * 112];      // offset/mask proj (bf16)
__device__ __nv_bfloat16 g_f[(size_t)P4 * 64];        // gated branch features (bf16)
__device__ float g_y[(size_t)P2 * 128];               // [y_l(64) ; y_r(64)] NHWC per batch
__device__ float g_part[256];                         // pooling sums [img][64]
__device__ float g_s[256];                            // SCA scale s[b][128]
__device__ __nv_bfloat16 g_wp[75776];                 // packed bf16 weights

// packed-weight segment offsets (elements)
#define OFF_PW1   0
#define OFF_VAL   8192
#define OFF_OM    24576
#define OFF_OUTP  38912
#define OFF_C4    55296
#define OFF_C5    71680

// ------------------------- bf16 helpers -------------------------
__device__ __forceinline__ uint32_t pk(float a, float b) {
    __nv_bfloat162 t = __floats2bfloat162_rn(a, b);
    return *reinterpret_cast<uint32_t*>(&t);
}
__device__ __forceinline__ float2 upk(uint32_t u) {
    __nv_bfloat162 t = *reinterpret_cast<__nv_bfloat162*>(&u);
    return __bfloat1622float2(t);
}
__device__ __forceinline__ float4 ld4bf(const __nv_bfloat16* p) {
    uint2 u = *(const uint2*)p;
    float2 fa = upk(u.x), fb = upk(u.y);
    return make_float4(fa.x, fa.y, fb.x, fb.y);
}
__device__ __forceinline__ void mma_bf16(float* c, const uint32_t* a, const uint32_t* b) {
    asm volatile(
        "mma.sync.aligned.m16n8k16.row.col.f32.bf16.bf16.f32 "
        "{%0,%1,%2,%3}, {%4,%5,%6,%7}, {%8,%9}, {%0,%1,%2,%3};"
        : "+f"(c[0]), "+f"(c[1]), "+f"(c[2]), "+f"(c[3])
        : "r"(a[0]), "r"(a[1]), "r"(a[2]), "r"(a[3]), "r"(b[0]), "r"(b[1]));
}
__device__ __forceinline__ void fma8(float* a, float w, uint4 u) {
    float2 f0 = upk(u.x), f1 = upk(u.y), f2 = upk(u.z), f3 = upk(u.w);
    a[0] += w * f0.x; a[1] += w * f0.y; a[2] += w * f1.x; a[3] += w * f1.y;
    a[4] += w * f2.x; a[5] += w * f2.y; a[6] += w * f3.x; a[7] += w * f3.y;
}

// ------------------------- weight pack + g_part zero + v border zero -------------------------
__global__ void __launch_bounds__(256) k_pack(const float* __restrict__ pw1,
                                              const float* __restrict__ val,
                                              const float* __restrict__ om,
                                              const float* __restrict__ outp,
                                              const float* __restrict__ c4,
                                              const float* __restrict__ c5) {
    int b = blockIdx.x;
    if (b < 296) {
        int i = b * 256 + threadIdx.x;
        if (b == 0) g_part[threadIdx.x] = 0.f;
        if (i >= 75776) return;
        float v;
        if (i < OFF_VAL)       v = pw1[i - OFF_PW1];
        else if (i < OFF_OM)   v = val[i - OFF_VAL];
        else if (i < OFF_OUTP) v = om[i - OFF_OM];
        else if (i < OFF_C4)   v = outp[i - OFF_OUTP];
        else if (i < OFF_C5)   v = c4[i - OFF_C4];
        else                   v = c5[i - OFF_C5];
        g_wp[i] = __float2bfloat16_rn(v);
    } else {
        // zero the 4-px border of g_vp: 2624 border pixels per image, 16 uint4 per px
        int i = (b - 296) * 256 + threadIdx.x;
        if (i >= 167936) return;
        int img = i / 41984;
        int rem = i - img * 41984;
        int bp = rem >> 4, w = rem & 15;
        int y, x;
        if (bp < 672) { y = bp / PW; x = bp - y * PW; }
        else if (bp < 1344) { int t = bp - 672; int yy = t / PW; y = 164 + yy; x = t - yy * PW; }
        else { int t = bp - 1344; y = 4 + (t >> 3); int xi = t & 7; x = (xi < 4) ? xi : 160 + xi; }
        ((uint4*)g_vp)[((size_t)img * PA + y * PW + x) * 16 + w] = make_uint4(0u, 0u, 0u, 0u);
    }
}

// ------------------------- kernel 1: LN + pw1 + val GEMM fused -------------------------
__global__ void __launch_bounds__(256) k_lnpw1v(const float* __restrict__ x_l,
                                                const float* __restrict__ x_r,
                                                const float* __restrict__ g1,
                                                const float* __restrict__ B1,
                                                const float* __restrict__ Bv) {
    extern __shared__ float sm[];
    float* Xf = sm;                            // 64*68 fp32
    float* mr = Xf + 64 * 68;                  // 128
    uint32_t* Xb = (uint32_t*)(mr + 128);      // 64*36 (bf16 pairs, K=64)
    uint32_t* Wb = Xb + 64 * 36;               // 128*36 (pw1 weights)
    uint32_t* Wv = Wb + 128 * 36;              // 128*68 (val weights, K=128)
    uint32_t* Hb = Wv + 128 * 68;              // 64*68  (h tile bf16)
    int tid = threadIdx.x;
    int base = blockIdx.x * 64;
    int img = base / HW;
    int pos = base - img * HW;
    const float* xp = (img < 2) ? (x_l + (size_t)img * HW * 64)
                                : (x_r + (size_t)(img - 2) * HW * 64);
    for (int i = tid; i < 64 * 64; i += 256) {
        int c = i >> 6, p = i & 63;
        Xf[p * 68 + c] = xp[(size_t)c * HW + pos + p];
    }
    const uint4* Wp1 = (const uint4*)(g_wp + OFF_PW1);
    for (int i = tid; i < 1024; i += 256) {
        int row = i >> 3, q = i & 7;
        uint4 u = __ldg(&Wp1[row * 8 + q]);
        Wb[row * 36 + q * 4]     = u.x;
        Wb[row * 36 + q * 4 + 1] = u.y;
        Wb[row * 36 + q * 4 + 2] = u.z;
        Wb[row * 36 + q * 4 + 3] = u.w;
    }
    const uint4* Wpv = (const uint4*)(g_wp + OFF_VAL);
    for (int i = tid; i < 2048; i += 256) {
        int row = i >> 4, q = i & 15;
        uint4 u = __ldg(&Wpv[row * 16 + q]);
        Wv[row * 68 + q * 4]     = u.x;
        Wv[row * 68 + q * 4 + 1] = u.y;
        Wv[row * 68 + q * 4 + 2] = u.z;
        Wv[row * 68 + q * 4 + 3] = u.w;
    }
    __syncthreads();
    if (tid < 64) {
        float s = 0.f, sq = 0.f;
        for (int c = 0; c < 64; c++) { float v = Xf[tid * 68 + c]; s += v; sq += v * v; }
        float m = s * (1.f / 64.f);
        float var = sq * (1.f / 64.f) - m * m;
        mr[tid] = m; mr[64 + tid] = rsqrtf(var + 1e-5f);
    }
    __syncthreads();
    for (int i = tid; i < 64 * 32; i += 256) {
        int p = i >> 5, q = i & 31;
        int k0 = q * 2;
        float f0 = (Xf[p * 68 + k0] - mr[p]) * mr[64 + p] * __ldg(&g1[k0]);
        float f1 = (Xf[p * 68 + k0 + 1] - mr[p]) * mr[64 + p] * __ldg(&g1[k0 + 1]);
        Xb[p * 36 + q] = pk(f0, f1);
    }
    __syncthreads();
    int wid = tid >> 5, lane = tid & 31;
    int wm = wid & 1, wn = wid >> 1;
    int gid = lane >> 2, tig = lane & 3;
    // ---- phase 1: h ----
    {
        float c[2][4][4];
#pragma unroll
        for (int nt = 0; nt < 4; nt++) {
            int o = wn * 32 + nt * 8 + 2 * tig;
            float b0 = B1[o], b1 = B1[o + 1];
#pragma unroll
            for (int mt = 0; mt < 2; mt++) {
                c[mt][nt][0] = b0; c[mt][nt][1] = b1;
                c[mt][nt][2] = b0; c[mt][nt][3] = b1;
            }
        }
#pragma unroll
        for (int kw = 0; kw < 32; kw += 8) {
            uint32_t A[2][4];
#pragma unroll
            for (int mt = 0; mt < 2; mt++) {
                int r = wm * 32 + mt * 16 + gid;
                A[mt][0] = Xb[r * 36 + kw + tig];
                A[mt][1] = Xb[(r + 8) * 36 + kw + tig];
                A[mt][2] = Xb[r * 36 + kw + 4 + tig];
                A[mt][3] = Xb[(r + 8) * 36 + kw + 4 + tig];
            }
#pragma unroll
            for (int nt = 0; nt < 4; nt++) {
                int n = wn * 32 + nt * 8 + gid;
                uint32_t Bf[2];
                Bf[0] = Wb[n * 36 + kw + tig];
                Bf[1] = Wb[n * 36 + kw + 4 + tig];
#pragma unroll
                for (int mt = 0; mt < 2; mt++) mma_bf16(c[mt][nt], A[mt], Bf);
            }
        }
        uint32_t* gh = (uint32_t*)g_h;
#pragma unroll
        for (int mt = 0; mt < 2; mt++) {
            int rl = wm * 32 + mt * 16 + gid;
            size_t r0 = base + rl;
#pragma unroll
            for (int nt = 0; nt < 4; nt++) {
                int o = wn * 32 + nt * 8 + 2 * tig;
                uint32_t w0 = pk(c[mt][nt][0], c[mt][nt][1]);
                uint32_t w1 = pk(c[mt][nt][2], c[mt][nt][3]);
                gh[r0 * 64 + o / 2] = w0;
                gh[(r0 + 8) * 64 + o / 2] = w1;
                Hb[rl * 68 + o / 2] = w0;
                Hb[(rl + 8) * 68 + o / 2] = w1;
            }
        }
    }
    __syncthreads();
    // ---- phase 2: v (stores into zero-padded layout) ----
    {
        float c[2][4][4];
#pragma unroll
        for (int nt = 0; nt < 4; nt++) {
            int o = wn * 32 + nt * 8 + 2 * tig;
            float b0 = Bv[o], b1 = Bv[o + 1];
#pragma unroll
            for (int mt = 0; mt < 2; mt++) {
                c[mt][nt][0] = b0; c[mt][nt][1] = b1;
                c[mt][nt][2] = b0; c[mt][nt][3] = b1;
            }
        }
#pragma unroll
        for (int kw = 0; kw < 64; kw += 8) {
            uint32_t A[2][4];
#pragma unroll
            for (int mt = 0; mt < 2; mt++) {
                int r = wm * 32 + mt * 16 + gid;
                A[mt][0] = Hb[r * 68 + kw + tig];
                A[mt][1] = Hb[(r + 8) * 68 + kw + tig];
                A[mt][2] = Hb[r * 68 + kw + 4 + tig];
                A[mt][3] = Hb[(r + 8) * 68 + kw + 4 + tig];
            }
#pragma unroll
            for (int nt = 0; nt < 4; nt++) {
                int n = wn * 32 + nt * 8 + gid;
                uint32_t Bf[2];
                Bf[0] = Wv[n * 68 + kw + tig];
                Bf[1] = Wv[n * 68 + kw + 4 + tig];
#pragma unroll
                for (int mt = 0; mt < 2; mt++) mma_bf16(c[mt][nt], A[mt], Bf);
            }
        }
        uint32_t* gv = (uint32_t*)g_vp;
#pragma unroll
        for (int mt = 0; mt < 2; mt++) {
            int rl = wm * 32 + mt * 16 + gid;
            int p0 = pos + rl, p1 = p0 + 8;
            int y0 = p0 / 160, x0 = p0 - y0 * 160;
            int y1 = p1 / 160, x1 = p1 - y1 * 160;
            size_t q0 = (size_t)img * PA + (y0 + 4) * PW + (x0 + 4);
            size_t q1 = (size_t)img * PA + (y1 + 4) * PW + (x1 + 4);
#pragma unroll
            for (int nt = 0; nt < 4; nt++) {
                int o = wn * 32 + nt * 8 + 2 * tig;
                gv[q0 * 64 + o / 2] = pk(c[mt][nt][0], c[mt][nt][1]);
                gv[q1 * 64 + o / 2] = pk(c[mt][nt][2], c[mt][nt][3]);
            }
        }
    }
}

// ------------------------- fused: depthwise 3x3 + om GEMM (128px x 112, K=128) -------------------------
__global__ void __launch_bounds__(256) k_dwom(const float* __restrict__ Wd,
                                              const float* __restrict__ Bd,
                                              const float* __restrict__ Bb) {
    const int N = 112;
    extern __shared__ uint32_t smu[];
    uint32_t* Xu = smu;                        // 128*68 words (dwc out, bf16)
    uint32_t* Wu = smu + 128 * 68;             // 128*68 words (om weights)
    float* wts = (float*)(Wu + 128 * 68);      // 9*128 dwc weights
    float* bds = wts + 9 * 128;                // 128 dwc bias
    int tid = threadIdx.x;
    size_t base = (size_t)blockIdx.x * 128;
    int img = (int)(base / HW);
    int pbase = (int)(base - (size_t)img * HW);
    for (int i = tid; i < 9 * 128; i += 256) wts[i] = __ldg(&Wd[i]);
    if (tid < 128) bds[tid] = __ldg(&Bd[tid]);
    const uint4* Wg = (const uint4*)(g_wp + OFF_OM);
    for (int i = tid; i < 2048; i += 256) {
        int row = i >> 4, q = i & 15;
        uint4 u = make_uint4(0u, 0u, 0u, 0u);
        if (row < N) u = __ldg(&Wg[row * 16 + q]);
        Wu[row * 68 + q * 4]     = u.x;
        Wu[row * 68 + q * 4 + 1] = u.y;
        Wu[row * 68 + q * 4 + 2] = u.z;
        Wu[row * 68 + q * 4 + 3] = u.w;
    }
    __syncthreads();
    const __nv_bfloat16* hb = g_h + (size_t)img * HW * 128;
    for (int it = tid; it < 4096; it += 256) {
        int px = it >> 5;
        int wg = it & 31;
        int c0 = wg * 4;
        int pos = pbase + px;
        int hh = pos / 160, ww = pos - hh * 160;
        float a0 = bds[c0], a1 = bds[c0 + 1], a2 = bds[c0 + 2], a3 = bds[c0 + 3];
#pragma unroll
        for (int dy = 0; dy < 3; dy++) {
            int y = hh + dy - 1;
            if ((unsigned)y >= 160u) continue;
            const __nv_bfloat16* rowp = hb + ((size_t)y * 160) * 128 + c0;
#pragma unroll
            for (int dx = 0; dx < 3; dx++) {
                int x = ww + dx - 1;
                if ((unsigned)x >= 160u) continue;
                float4 v = ld4bf(&rowp[(size_t)x * 128]);
                float4 wv = *(const float4*)&wts[(dy * 3 + dx) * 128 + c0];
                a0 += v.x * wv.x; a1 += v.y * wv.y; a2 += v.z * wv.z; a3 += v.w * wv.w;
            }
        }
        Xu[px * 68 + wg * 2]     = pk(a0, a1);
        Xu[px * 68 + wg * 2 + 1] = pk(a2, a3);
    }
    __syncthreads();
    int wid = tid >> 5, lane = tid & 31;
    int wm = wid & 3, wn = wid >> 2;
    int gid = lane >> 2, tig = lane & 3;
    float c[2][8][4];
#pragma unroll
    for (int nt = 0; nt < 8; nt++) {
        int o = wn * 64 + nt * 8 + 2 * tig;
        float b0 = (o < N) ? Bb[o] : 0.f;
        float b1 = (o + 1 < N) ? Bb[o + 1] : 0.f;
#pragma unroll
        for (int mt = 0; mt < 2; mt++) {
            c[mt][nt][0] = b0; c[mt][nt][1] = b1;
            c[mt][nt][2] = b0; c[mt][nt][3] = b1;
        }
    }
#pragma unroll
    for (int kw = 0; kw < 64; kw += 8) {
        uint32_t A[2][4];
#pragma unroll
        for (int mt = 0; mt < 2; mt++) {
            int r = wm * 32 + mt * 16 + gid;
            A[mt][0] = Xu[r * 68 + kw + tig];
            A[mt][1] = Xu[(r + 8) * 68 + kw + tig];
            A[mt][2] = Xu[r * 68 + kw + 4 + tig];
            A[mt][3] = Xu[(r + 8) * 68 + kw + 4 + tig];
        }
        uint32_t Bf[8][2];
#pragma unroll
        for (int nt = 0; nt < 8; nt++) {
            int n = wn * 64 + nt * 8 + gid;
            Bf[nt][0] = Wu[n * 68 + kw + tig];
            Bf[nt][1] = Wu[n * 68 + kw + 4 + tig];
        }
#pragma unroll
        for (int mt = 0; mt < 2; mt++)
#pragma unroll
            for (int nt = 0; nt < 8; nt++)
                mma_bf16(c[mt][nt], A[mt], Bf[nt]);
    }
    uint32_t* Yu = (uint32_t*)g_om;
#pragma unroll
    for (int mt = 0; mt < 2; mt++) {
        size_t r0 = base + wm * 32 + mt * 16 + gid;
#pragma unroll
        for (int nt = 0; nt < 8; nt++) {
            int o = wn * 64 + nt * 8 + 2 * tig;
            if (o < N) {
                Yu[r0 * 56 + o / 2] = pk(c[mt][nt][0], c[mt][nt][1]);
                Yu[(r0 + 8) * 56 + o / 2] = pk(c[mt][nt][2], c[mt][nt][3]);
            }
        }
    }
}

// ------------------------- fused: deform sample + outp GEMM + gate + pool partial -------------------------
// smem layout: Xb [0,4352) | OMt/Wb overlay [4352,13056) | pacc [13056,13120)
__global__ void __launch_bounds__(256) k_souter(const float* __restrict__ Bo) {
    extern __shared__ uint32_t smu[];
    uint32_t* Xb = smu;                         // 64*68 words (sampled bf16)
    uint32_t* OMt = smu + 4352;                 // 64*56 words (om tile, phase 1)
    uint32_t* Wb = smu + 4352;                  // 128*68 words (outp weights, phase 2 overlay)
    float* pacc = (float*)(smu + 13056);        // 64 floats
    int tid = threadIdx.x;
    int base = blockIdx.x * 64;
    int img = base / HW;
    int pbase = base - img * HW;
    if (tid < 64) pacc[tid] = 0.f;
    // stage om tile (coalesced)
    {
        const uint32_t* oms = (const uint32_t*)g_om + ((size_t)img * HW + pbase) * 56;
        for (int i = tid; i < 3584; i += 256) OMt[i] = __ldg(&oms[i]);
    }
    __syncthreads();
    // ---- sampling: warp = 8 px (2 at a time); lane = (pxh, g, c8) -> 8 channels ----
    // zero-padded v: no bounds checks / masks needed (OOB taps read zeros)
    int wrp = tid >> 5, lane = tid & 31;
    int pxh = lane >> 4;
    int g = (lane >> 2) & 3;
    int c8 = lane & 3;
    const uint4* vp = (const uint4*)g_vp + (size_t)img * PA * 16 + g * 4 + c8;
    for (int pp = 0; pp < 4; pp++) {
        int px = wrp * 8 + pp * 2 + pxh;
        int pos = pbase + px;
        int hh = pos / 160, ww = pos - hh * 160;
        const uint32_t* omp = OMt + px * 56;
        float a[8] = {0.f, 0.f, 0.f, 0.f, 0.f, 0.f, 0.f, 0.f};
#pragma unroll
        for (int k = 0; k < 9; k++) {
            int w0i = (g * 27 + 3 * k) >> 1;
            float2 f0 = upk(omp[w0i]);
            float2 f1 = upk(omp[w0i + 1]);
            bool odd = ((g + k) & 1);
            float ox = odd ? f0.y : f0.x;
            float oy = odd ? f1.x : f0.y;
            float mk = odd ? f1.y : f1.x;
            float fx = fminf(fmaxf((float)(ww + (k % 3) - 1) + ox, -3.f), 162.f);
            float fy = fminf(fmaxf((float)(hh + (k / 3) - 1) + oy, -3.f), 162.f);
            float x0f = floorf(fx), y0f = floorf(fy);
            float tx = fx - x0f, ty = fy - y0f;
            int r00 = ((int)y0f + 4) * PW + (int)x0f + 4;
            float w00 = (1.f - tx) * (1.f - ty) * mk;
            float w01 = tx * (1.f - ty) * mk;
            float w10 = (1.f - tx) * ty * mk;
            float w11 = tx * ty * mk;
            fma8(a, w00, __ldg(&vp[r00 * 16]));
            fma8(a, w01, __ldg(&vp[(r00 + 1) * 16]));
            fma8(a, w10, __ldg(&vp[(r00 + PW) * 16]));
            fma8(a, w11, __ldg(&vp[(r00 + PW + 1) * 16]));
        }
        int cw = g * 16 + c8 * 4;   // channel word base within row
#pragma unroll
        for (int j = 0; j < 4; j++)
            Xb[px * 68 + cw + j] = pk(a[2 * j], a[2 * j + 1]);
    }
    __syncthreads();
    // load outp weights (overlays OMt)
    const uint4* Wg = (const uint4*)(g_wp + OFF_OUTP);
    for (int i = tid; i < 2048; i += 256) {
        int row = i >> 4, q = i & 15;
        uint4 u = __ldg(&Wg[row * 16 + q]);
        Wb[row * 68 + q * 4]     = u.x;
        Wb[row * 68 + q * 4 + 1] = u.y;
        Wb[row * 68 + q * 4 + 2] = u.z;
        Wb[row * 68 + q * 4 + 3] = u.w;
    }
    __syncthreads();
    // ---- GEMM + gate + pool partial ----
    int wm = wrp & 1, wn = wrp >> 1;
    int gid = lane >> 2, tig = lane & 3;
    float c[2][4][4];
#pragma unroll
    for (int nt = 0; nt < 4; nt++) {
        int o = wn * 16 + (nt & 1) * 8 + (nt >> 1) * 64 + 2 * tig;
        float b0 = Bo[o], b1 = Bo[o + 1];
#pragma unroll
        for (int mt = 0; mt < 2; mt++) {
            c[mt][nt][0] = b0; c[mt][nt][1] = b1;
            c[mt][nt][2] = b0; c[mt][nt][3] = b1;
        }
    }
#pragma unroll
    for (int kw = 0; kw < 64; kw += 8) {
        uint32_t A[2][4];
#pragma unroll
        for (int mt = 0; mt < 2; mt++) {
            int r = wm * 32 + mt * 16 + gid;
            A[mt][0] = Xb[r * 68 + kw + tig];
            A[mt][1] = Xb[(r + 8) * 68 + kw + tig];
            A[mt][2] = Xb[r * 68 + kw + 4 + tig];
            A[mt][3] = Xb[(r + 8) * 68 + kw + 4 + tig];
        }
#pragma unroll
        for (int nt = 0; nt < 4; nt++) {
            int n = wn * 16 + (nt & 1) * 8 + (nt >> 1) * 64 + gid;
            uint32_t Bf[2];
            Bf[0] = Wb[n * 68 + kw + tig];
            Bf[1] = Wb[n * 68 + kw + 4 + tig];
#pragma unroll
            for (int mt = 0; mt < 2; mt++) mma_bf16(c[mt][nt], A[mt], Bf);
        }
    }
    uint32_t* gf = (uint32_t*)g_f;
#pragma unroll
    for (int ntp = 0; ntp < 2; ntp++) {
        int o = wn * 16 + ntp * 8 + 2 * tig;
        float s0 = 0.f, s1 = 0.f;
#pragma unroll
        for (int mt = 0; mt < 2; mt++) {
            size_t r0 = base + wm * 32 + mt * 16 + gid;
            float p00 = c[mt][ntp][0] * c[mt][ntp + 2][0];
            float p01 = c[mt][ntp][1] * c[mt][ntp + 2][1];
            float p10 = c[mt][ntp][2] * c[mt][ntp + 2][2];
            float p11 = c[mt][ntp][3] * c[mt][ntp + 2][3];
            gf[r0 * 32 + o / 2] = pk(p00, p01);
            gf[(r0 + 8) * 32 + o / 2] = pk(p10, p11);
            s0 += p00 + p10;
            s1 += p01 + p11;
        }
        atomicAdd(&pacc[o], s0);
        atomicAdd(&pacc[o + 1], s1);
    }
    __syncthreads();
    if (tid < 64) atomicAdd(&g_part[img * 64 + tid], pacc[tid]);
}

// ------------------------- finish pooling + SCA projection -------------------------
__global__ void __launch_bounds__(256) k_sca(const float* __restrict__ sw, const float* __restrict__ sb) {
    __shared__ float shp[256];
    int tid = threadIdx.x;
    int b = tid >> 7, c = tid & 127;
    int img = (c < 64) ? b : (2 + b);
    int cc = c & 63;
    shp[tid] = g_part[img * 64 + cc] * (1.f / (float)HW);
    __syncthreads();
    float acc = __ldg(&sb[c]);
    for (int k = 0; k < 128; k++) acc += shp[b * 128 + k] * __ldg(&sw[c * 128 + k]);
    g_s[tid] = acc;
}

// ------------------------- SCA-folded conv3 + dual residual -> g_y -------------------------
__global__ void __launch_bounds__(256) k_conv3_y(const float* __restrict__ W3,
                                                 const float* __restrict__ B3,
                                                 const float* __restrict__ beta,
                                                 const float* __restrict__ x_l,
                                                 const float* __restrict__ x_r) {
    extern __shared__ float sm[];
    float* Fs = sm;              // 64*132
    float* W3s = sm + 64 * 132;  // 64*128 (scale-folded)
    int tid = threadIdx.x;
    int base = blockIdx.x * 64;
    int b = base / HW;
    int pos = base - b * HW;
    const uint32_t* gf = (const uint32_t*)g_f;
    for (int i = tid; i < 64 * 64; i += 256) {
        int p = i >> 6, w = i & 63;
        int imgX = (w < 32) ? b : (2 + b);
        float2 f = upk(gf[((size_t)imgX * HW + pos + p) * 32 + (w & 31)]);
        Fs[p * 132 + 2 * w] = f.x;
        Fs[p * 132 + 2 * w + 1] = f.y;
    }
    for (int i = tid; i < 64 * 128; i += 256) {
        int o = i & 127;
        W3s[i] = W3[i] * g_s[b * 128 + o];
    }
    __syncthreads();
    int pr = tid & 15, og = tid >> 4;
    float acc[4][4];
#pragma unroll
    for (int j = 0; j < 4; j++) {
        float bv = B3[og * 4 + j];
#pragma unroll
        for (int i = 0; i < 4; i++) acc[i][j] = bv;
    }
#pragma unroll 4
    for (int k = 0; k < 128; k += 4) {
        float4 xv[4];
#pragma unroll
        for (int i = 0; i < 4; i++) xv[i] = *(const float4*)&Fs[(pr + 16 * i) * 132 + k];
#pragma unroll
        for (int j = 0; j < 4; j++) {
            float4 wv = *(const float4*)&W3s[(og * 4 + j) * 128 + k];
#pragma unroll
            for (int i = 0; i < 4; i++)
                acc[i][j] += xv[i].x * wv.x + xv[i].y * wv.y + xv[i].z * wv.z + xv[i].w * wv.w;
        }
    }
#pragma unroll
    for (int i = 0; i < 4; i++) {
        int p = pr + 16 * i;
#pragma unroll
        for (int j = 0; j < 4; j++) {
            int jj = og * 4 + j;
            float bt = __ldg(&beta[jj]);
            float x3 = acc[i][j] * bt;
            float xl = x_l[((size_t)b * 64 + jj) * HW + pos + p];
            float xr = x_r[((size_t)b * 64 + jj) * HW + pos + p];
            g_y[(size_t)(base + p) * 128 + jj] = xl + x3;
            g_y[(size_t)(base + p) * 128 + 64 + jj] = xr + x3;
        }
    }
}

// ------------------------- LN2 + conv4 + gate + conv5 + final residuals -> out -------------------------
__global__ void __launch_bounds__(256) k_ln2c4c5(const float* __restrict__ g2,
                                                 const float* __restrict__ B4,
                                                 const float* __restrict__ B5,
                                                 const float* __restrict__ gamma,
                                                 float* __restrict__ out) {
    extern __shared__ float sm[];
    float* Yf = sm;                                 // 64*132 fp32
    uint32_t* Yb = (uint32_t*)(sm + 64 * 132);      // 64*68 words
    uint32_t* Wb = Yb + 64 * 68;                    // 128*68 words (conv4)
    uint32_t* Zb = Wb + 128 * 68;                   // 64*36 words (zg bf16)
    uint32_t* W5b = Zb + 64 * 36;                   // 64*36 words (conv5)
    float* mr = (float*)(W5b + 64 * 36);            // 128
    int tid = threadIdx.x;
    int base = blockIdx.x * 64;
    int b = base / HW;
    int pos = base - b * HW;
    for (int i = tid; i < 64 * 128; i += 256) {
        int p = i >> 7, c = i & 127;
        Yf[p * 132 + c] = g_y[(size_t)(base + p) * 128 + c];
    }
    const uint4* Wg = (const uint4*)(g_wp + OFF_C4);
    for (int i = tid; i < 2048; i += 256) {
        int row = i >> 4, q = i & 15;
        uint4 u = __ldg(&Wg[row * 16 + q]);
        Wb[row * 68 + q * 4]     = u.x;
        Wb[row * 68 + q * 4 + 1] = u.y;
        Wb[row * 68 + q * 4 + 2] = u.z;
        Wb[row * 68 + q * 4 + 3] = u.w;
    }
    const uint4* W5g = (const uint4*)(g_wp + OFF_C5);
    for (int i = tid; i < 512; i += 256) {
        int row = i >> 3, q = i & 7;
        uint4 u = __ldg(&W5g[row * 8 + q]);
        W5b[row * 36 + q * 4]     = u.x;
        W5b[row * 36 + q * 4 + 1] = u.y;
        W5b[row * 36 + q * 4 + 2] = u.z;
        W5b[row * 36 + q * 4 + 3] = u.w;
    }
    __syncthreads();
    if (tid < 64) {
        float s = 0.f, sq = 0.f;
        for (int c = 0; c < 128; c++) { float v = Yf[tid * 132 + c]; s += v; sq += v * v; }
        float m = s * (1.f / 128.f);
        float var = sq * (1.f / 128.f) - m * m;
        mr[tid] = m; mr[64 + tid] = rsqrtf(var + 1e-5f);
    }
    __syncthreads();
    for (int i = tid; i < 64 * 64; i += 256) {
        int p = i >> 6, q = i & 63;
        int k0 = q * 2;
        float f0 = (Yf[p * 132 + k0] - mr[p]) * mr[64 + p] * __ldg(&g2[k0]);
        float f1 = (Yf[p * 132 + k0 + 1] - mr[p]) * mr[64 + p] * __ldg(&g2[k0 + 1]);
        Yb[p * 68 + q] = pk(f0, f1);
    }
    __syncthreads();
    int wid = tid >> 5, lane = tid & 31;
    int wm = wid & 1, wn = wid >> 1;
    int gid = lane >> 2, tig = lane & 3;
    // ---- conv4 + gate -> Zb ----
    {
        float c[2][4][4];
#pragma unroll
        for (int nt = 0; nt < 4; nt++) {
            int o = wn * 16 + (nt & 1) * 8 + (nt >> 1) * 64 + 2 * tig;
            float b0 = B4[o], b1 = B4[o + 1];
#pragma unroll
            for (int mt = 0; mt < 2; mt++) {
                c[mt][nt][0] = b0; c[mt][nt][1] = b1;
                c[mt][nt][2] = b0; c[mt][nt][3] = b1;
            }
        }
#pragma unroll
        for (int kw = 0; kw < 64; kw += 8) {
            uint32_t A[2][4];
#pragma unroll
            for (int mt = 0; mt < 2; mt++) {
                int r = wm * 32 + mt * 16 + gid;
                A[mt][0] = Yb[r * 68 + kw + tig];
                A[mt][1] = Yb[(r + 8) * 68 + kw + tig];
                A[mt][2] = Yb[r * 68 + kw + 4 + tig];
                A[mt][3] = Yb[(r + 8) * 68 + kw + 4 + tig];
            }
#pragma unroll
            for (int nt = 0; nt < 4; nt++) {
                int n = wn * 16 + (nt & 1) * 8 + (nt >> 1) * 64 + gid;
                uint32_t Bf[2];
                Bf[0] = Wb[n * 68 + kw + tig];
                Bf[1] = Wb[n * 68 + kw + 4 + tig];
#pragma unroll
                for (int mt = 0; mt < 2; mt++) mma_bf16(c[mt][nt], A[mt], Bf);
            }
        }
#pragma unroll
        for (int mt = 0; mt < 2; mt++) {
            int rl = wm * 32 + mt * 16 + gid;
#pragma unroll
            for (int ntp = 0; ntp < 2; ntp++) {
                int o = wn * 16 + ntp * 8 + 2 * tig;
                Zb[rl * 36 + o / 2] =
                    pk(c[mt][ntp][0] * c[mt][ntp + 2][0], c[mt][ntp][1] * c[mt][ntp + 2][1]);
                Zb[(rl + 8) * 36 + o / 2] =
                    pk(c[mt][ntp][2] * c[mt][ntp + 2][2], c[mt][ntp][3] * c[mt][ntp + 2][3]);
            }
        }
    }
    __syncthreads();
    // ---- conv5 (K=64) + residual epilogue ----
    {
        float c[2][2][4];
#pragma unroll
        for (int nt = 0; nt < 2; nt++) {
            int o = wn * 16 + nt * 8 + 2 * tig;
            float b0 = B5[o], b1 = B5[o + 1];
#pragma unroll
            for (int mt = 0; mt < 2; mt++) {
                c[mt][nt][0] = b0; c[mt][nt][1] = b1;
                c[mt][nt][2] = b0; c[mt][nt][3] = b1;
            }
        }
#pragma unroll
        for (int kw = 0; kw < 32; kw += 8) {
            uint32_t A[2][4];
#pragma unroll
            for (int mt = 0; mt < 2; mt++) {
                int r = wm * 32 + mt * 16 + gid;
                A[mt][0] = Zb[r * 36 + kw + tig];
                A[mt][1] = Zb[(r + 8) * 36 + kw + tig];
                A[mt][2] = Zb[r * 36 + kw + 4 + tig];
                A[mt][3] = Zb[(r + 8) * 36 + kw + 4 + tig];
            }
#pragma unroll
            for (int nt = 0; nt < 2; nt++) {
                int n = wn * 16 + nt * 8 + gid;
                uint32_t Bf[2];
                Bf[0] = W5b[n * 36 + kw + tig];
                Bf[1] = W5b[n * 36 + kw + 4 + tig];
#pragma unroll
                for (int mt = 0; mt < 2; mt++) mma_bf16(c[mt][nt], A[mt], Bf);
            }
        }
        const size_t HALF = (size_t)2 * 64 * HW;
#pragma unroll
        for (int mt = 0; mt < 2; mt++) {
            int p0 = wm * 32 + mt * 16 + gid;
#pragma unroll
            for (int nt = 0; nt < 2; nt++) {
                int cc = wn * 16 + nt * 8 + 2 * tig;
                float gm0 = __ldg(&gamma[cc]), gm1 = __ldg(&gamma[cc + 1]);
#pragma unroll
                for (int rr = 0; rr < 2; rr++) {
                    int p = p0 + rr * 8;
                    float z0 = c[mt][nt][rr * 2] * gm0;
                    float z1 = c[mt][nt][rr * 2 + 1] * gm1;
                    size_t o0 = ((size_t)b * 64 + cc) * HW + pos + p;
                    size_t o1 = ((size_t)b * 64 + cc + 1) * HW + pos + p;
                    out[o0] = Yf[p * 132 + cc] + z0;
                    out[o1] = Yf[p * 132 + cc + 1] + z1;
                    out[HALF + o0] = Yf[p * 132 + 64 + cc] + z0;
                    out[HALF + o1] = Yf[p * 132 + 64 + cc + 1] + z1;
                }
            }
        }
    }
}

// ------------------------- host -------------------------
extern "C" void kernel_launch(void* const* d_in, const int* in_sizes, int n_in,
                              void* d_out, int out_size) {
    const float* x_l     = (const float*)d_in[0];
    const float* x_r     = (const float*)d_in[1];
    const float* ln1_g   = (const float*)d_in[2];
    const float* pw1_w   = (const float*)d_in[3];
    const float* pw1_b   = (const float*)d_in[4];
    const float* val_w   = (const float*)d_in[5];
    const float* val_b   = (const float*)d_in[6];
    const float* dwc_w   = (const float*)d_in[7];
    const float* dwc_b   = (const float*)d_in[8];
    const float* om_w    = (const float*)d_in[9];
    const float* om_b    = (const float*)d_in[10];
    const float* outp_w  = (const float*)d_in[11];
    const float* outp_b  = (const float*)d_in[12];
    const float* sca_w   = (const float*)d_in[13];
    const float* sca_b   = (const float*)d_in[14];
    const float* conv3_w = (const float*)d_in[15];
    const float* conv3_b = (const float*)d_in[16];
    const float* norm2_g = (const float*)d_in[17];
    const float* conv4_w = (const float*)d_in[18];
    const float* conv4_b = (const float*)d_in[19];
    const float* conv5_w = (const float*)d_in[20];
    const float* conv5_b = (const float*)d_in[21];
    const float* beta    = (const float*)d_in[22];
    const float* gamma   = (const float*)d_in[23];
    float* out = (float*)d_out;

    const int SM_LNPW1V = (64 * 68 + 128 + 64 * 36 + 128 * 36 + 128 * 68 + 64 * 68) * 4;
    const int SM_DWOM   = (2 * 128 * 68 + 9 * 128 + 128) * 4;
    const int SM_SOUT   = 13120 * 4;
    const int SM_C3     = (64 * 132 + 64 * 128) * 4;
    const int SM_L245   = (64 * 132 + 64 * 68 + 128 * 68 + 64 * 36 + 64 * 36 + 128) * 4;

    cudaFuncSetAttribute(k_lnpw1v,  cudaFuncAttributeMaxDynamicSharedMemorySize, SM_LNPW1V);
    cudaFuncSetAttribute(k_dwom,    cudaFuncAttributeMaxDynamicSharedMemorySize, SM_DWOM);
    cudaFuncSetAttribute(k_souter,  cudaFuncAttributeMaxDynamicSharedMemorySize, SM_SOUT);
    cudaFuncSetAttribute(k_conv3_y, cudaFuncAttributeMaxDynamicSharedMemorySize, SM_C3);
    cudaFuncSetAttribute(k_ln2c4c5, cudaFuncAttributeMaxDynamicSharedMemorySize, SM_L245);

    k_pack    <<<952, 256>>>(pw1_w, val_w, om_w, outp_w, conv4_w, conv5_w);
    k_lnpw1v  <<<P4 / 64, 256, SM_LNPW1V>>>(x_l, x_r, ln1_g, pw1_b, val_b);
    k_dwom    <<<P4 / 128, 256, SM_DWOM>>>(dwc_w, dwc_b, om_b);
    k_souter  <<<P4 / 64, 256, SM_SOUT>>>(outp_b);
    k_sca     <<<1, 256>>>(sca_w, sca_b);
    k_conv3_y <<<P2 / 64, 256, SM_C3>>>(conv3_w, conv3_b, beta, x_l, x_r);
    k_ln2c4c5 <<<P2 / 64, 256, SM_L245>>>(norm2_g, conv4_b, conv5_b, gamma, out);
}